// round 1
// baseline (speedup 1.0000x reference)
#include <cuda_runtime.h>
#include <cuda_bf16.h>
#include <math_constants.h>

#define Nn 50000
#define Ee 800000
#define Hh 64
#define EDd 32
#define Ll 3
#define Gg 256
#define OUTd 32

// ---------------- static device scratch (no allocations allowed) ----------------
__device__ float d_QKVS[Nn * 256];   // per-layer q|k|v|skip, 64 cols each
__device__ float d_H[Nn * 64];       // node features
__device__ float d_ALPHA[Ee];        // per-edge logits -> exp weights
__device__ int   d_CNT[Nn];
__device__ int   d_CUR[Nn];
__device__ int   d_OFF[Nn + 1];
__device__ int   d_EID[Ee];          // edge ids sorted by dst (CSR)
__device__ float d_ET[10 * 64];      // per-layer edge-type table
__device__ unsigned d_GKEY[Gg];
__device__ float d_GDEN[Gg];
__device__ float d_OSUM[Gg * OUTd];
__device__ float d_GATE[Nn];
__device__ float d_GP[Nn];
__device__ float d_Y[Nn * OUTd];

// ---------------- helpers ----------------
__device__ __forceinline__ unsigned fkey(float f) {
    unsigned u = __float_as_uint(f);
    return (u & 0x80000000u) ? ~u : (u | 0x80000000u);
}
__device__ __forceinline__ float fdecode(unsigned k) {
    return (k & 0x80000000u) ? __uint_as_float(k & 0x7fffffffu) : __uint_as_float(~k);
}

// ---------------- init / zero ----------------
__global__ void k_init() {
    int i = blockIdx.x * blockDim.x + threadIdx.x;
    if (i < Nn) { d_CNT[i] = 0; d_CUR[i] = 0; }
    if (i < Gg) { d_GKEY[i] = 0u; d_GDEN[i] = 0.f; }
    if (i < Gg * OUTd) d_OSUM[i] = 0.f;
}

// ---------------- node embedding ----------------
__global__ void k_embed(const int* __restrict__ x, const float* __restrict__ node_emb) {
    int i = blockIdx.x * blockDim.x + threadIdx.x;
    if (i >= Nn * 64) return;
    int n = i >> 6, c = i & 63;
    d_H[i] = node_emb[x[n] * 64 + c];
}

// ---------------- CSR build ----------------
__global__ void k_hist(const int* __restrict__ dst) {
    int e = blockIdx.x * blockDim.x + threadIdx.x;
    if (e < Ee) atomicAdd(&d_CNT[dst[e]], 1);
}

__global__ void k_scan() {
    __shared__ int sh[1024];
    __shared__ int carry;
    int t = threadIdx.x;
    if (t == 0) carry = 0;
    __syncthreads();
    for (int base = 0; base < Nn; base += 1024) {
        int i = base + t;
        int v = (i < Nn) ? d_CNT[i] : 0;
        sh[t] = v;
        __syncthreads();
        for (int o = 1; o < 1024; o <<= 1) {
            int tmp = (t >= o) ? sh[t - o] : 0;
            __syncthreads();
            sh[t] += tmp;
            __syncthreads();
        }
        if (i < Nn) d_OFF[i] = carry + sh[t] - v;
        int bt = sh[1023];
        __syncthreads();
        if (t == 0) carry += bt;
        __syncthreads();
    }
    if (t == 0) d_OFF[Nn] = carry;
}

__global__ void k_scatter(const int* __restrict__ dst) {
    int e = blockIdx.x * blockDim.x + threadIdx.x;
    if (e >= Ee) return;
    int d = dst[e];
    int p = atomicAdd(&d_CUR[d], 1);
    d_EID[d_OFF[d] + p] = e;
}

// ---------------- per-layer edge-type table: ET[type] = edge_emb[type] @ We[l] ----------------
__global__ void k_etab(const float* __restrict__ edge_emb, const float* __restrict__ We, int l) {
    int t = threadIdx.x;                 // 640 threads
    if (t >= 640) return;
    int ty = t >> 6, c = t & 63;
    const float* W = We + l * (EDd * 64);
    float s = 0.f;
    #pragma unroll
    for (int j = 0; j < EDd; j++) s += edge_emb[ty * EDd + j] * W[j * 64 + c];
    d_ET[t] = s;
}

// ---------------- fused q,k,v,skip GEMM: QKVS = H @ [Wq|Wk|Wv|Wskip] + b ----------------
// block: 256 threads, 32 nodes x 256 cols. dyn smem: Wc[64*256] | bc[256] | hs[32*64]
__global__ void k_gemm(const float* __restrict__ Wq, const float* __restrict__ Wk,
                       const float* __restrict__ Wv, const float* __restrict__ Ws,
                       const float* __restrict__ bq, const float* __restrict__ bk,
                       const float* __restrict__ bv, const float* __restrict__ bs, int l) {
    extern __shared__ float smem[];
    float* Wc = smem;              // 16384 floats
    float* bc = smem + 16384;      // 256
    float* hs = smem + 16640;      // 2048
    int t = threadIdx.x;

    const float* wsrc[1];
    // load 4 weight matrices into combined [64][256]
    {
        const float* W;
        for (int m = 0; m < 4; m++) {
            W = (m == 0 ? Wq : m == 1 ? Wk : m == 2 ? Wv : Ws) + l * 4096;
            for (int i = t; i < 4096; i += 256) {
                int kk = i >> 6, cc = i & 63;
                Wc[kk * 256 + m * 64 + cc] = W[kk * 64 + cc];
            }
        }
        const float* B = (t < 64) ? bq : (t < 128) ? bk : (t < 192) ? bv : bs;
        bc[t] = B[l * 64 + (t & 63)];
    }
    (void)wsrc;
    int node0 = blockIdx.x * 32;
    for (int i = t; i < 32 * 64; i += 256) {
        int n = i >> 6, kk = i & 63;
        int gn = node0 + n;
        hs[i] = (gn < Nn) ? d_H[gn * 64 + kk] : 0.f;
    }
    __syncthreads();

    int lane = t & 31, warp = t >> 5;   // warp owns nodes warp*4 .. +4; lane owns cols lane+32j
    float acc[4][8];
    #pragma unroll
    for (int i = 0; i < 4; i++)
        #pragma unroll
        for (int j = 0; j < 8; j++) acc[i][j] = 0.f;

    #pragma unroll 8
    for (int kk = 0; kk < 64; kk++) {
        float hv[4];
        #pragma unroll
        for (int i = 0; i < 4; i++) hv[i] = hs[(warp * 4 + i) * 64 + kk];   // broadcast
        #pragma unroll
        for (int j = 0; j < 8; j++) {
            float wv = Wc[kk * 256 + lane + 32 * j];                        // conflict-free
            #pragma unroll
            for (int i = 0; i < 4; i++) acc[i][j] += hv[i] * wv;
        }
    }
    #pragma unroll
    for (int i = 0; i < 4; i++) {
        int gn = node0 + warp * 4 + i;
        if (gn < Nn) {
            #pragma unroll
            for (int j = 0; j < 8; j++) {
                int c = lane + 32 * j;
                d_QKVS[gn * 256 + c] = acc[i][j] + bc[c];
            }
        }
    }
}

// ---------------- fused edge pass: alpha, softmax, aggregate, skip+relu. warp per dst node ----------------
__global__ void k_edge(const int* __restrict__ src, const int* __restrict__ attr) {
    __shared__ float et[640];
    for (int i = threadIdx.x; i < 640; i += blockDim.x) et[i] = d_ET[i];
    __syncthreads();

    int n = (blockIdx.x * blockDim.x + threadIdx.x) >> 5;
    int lane = threadIdx.x & 31;
    if (n >= Nn) return;
    int s0 = d_OFF[n], s1 = d_OFF[n + 1];

    float q0 = d_QKVS[n * 256 + lane];
    float q1 = d_QKVS[n * 256 + 32 + lane];

    // pass 1: logits + running max
    float mx = -CUDART_INF_F;
    for (int i = s0; i < s1; i++) {
        int e = d_EID[i];
        int s = src[e], ty = attr[e];
        float k0 = d_QKVS[s * 256 + 64 + lane] + et[ty * 64 + lane];
        float k1 = d_QKVS[s * 256 + 96 + lane] + et[ty * 64 + 32 + lane];
        float d = q0 * k0 + q1 * k1;
        #pragma unroll
        for (int o = 16; o; o >>= 1) d += __shfl_xor_sync(0xffffffffu, d, o);
        d *= 0.125f;                    // 1/sqrt(64)
        if (lane == 0) d_ALPHA[e] = d;
        mx = fmaxf(mx, d);
    }
    __threadfence_block();
    __syncwarp();

    // pass 2: exp + sum (one exp per edge, lane-strided)
    float sum = 0.f;
    for (int i = s0 + lane; i < s1; i += 32) {
        int e = d_EID[i];
        float p = __expf(d_ALPHA[e] - mx);
        d_ALPHA[e] = p;
        sum += p;
    }
    #pragma unroll
    for (int o = 16; o; o >>= 1) sum += __shfl_xor_sync(0xffffffffu, sum, o);
    __threadfence_block();
    __syncwarp();
    float inv = (s1 > s0) ? 1.f / sum : 0.f;

    // pass 3: weighted aggregation of (v[src] + et)
    float a0 = 0.f, a1 = 0.f;
    for (int i = s0; i < s1; i++) {
        int e = d_EID[i];
        int s = src[e], ty = attr[e];
        float p = d_ALPHA[e];
        a0 += (d_QKVS[s * 256 + 128 + lane] + et[ty * 64 + lane]) * p;
        a1 += (d_QKVS[s * 256 + 160 + lane] + et[ty * 64 + 32 + lane]) * p;
    }
    float h0 = a0 * inv + d_QKVS[n * 256 + 192 + lane];
    float h1 = a1 * inv + d_QKVS[n * 256 + 224 + lane];
    d_H[n * 64 + lane] = fmaxf(h0, 0.f);
    d_H[n * 64 + 32 + lane] = fmaxf(h1, 0.f);
}

// ---------------- readout ----------------
// y = h @ out_W + out_b : thread per (node, col), 8 nodes per block
__global__ void k_y(const float* __restrict__ out_W, const float* __restrict__ out_b) {
    __shared__ float Wm[64 * OUTd];
    __shared__ float bb[OUTd];
    for (int i = threadIdx.x; i < 64 * OUTd; i += 256) Wm[i] = out_W[i];
    if (threadIdx.x < OUTd) bb[threadIdx.x] = out_b[threadIdx.x];
    __syncthreads();
    int n = blockIdx.x * 8 + (threadIdx.x >> 5);
    int c = threadIdx.x & 31;
    if (n >= Nn) return;
    float s = bb[c];
    #pragma unroll 8
    for (int kk = 0; kk < 64; kk++) s += d_H[n * 64 + kk] * Wm[kk * OUTd + c];
    d_Y[n * OUTd + c] = s;
}

// gate per node + per-graph max (warp per node)
__global__ void k_gate(const float* __restrict__ gW, const float* __restrict__ gb,
                       const int* __restrict__ batch) {
    int n = (blockIdx.x * blockDim.x + threadIdx.x) >> 5;
    int lane = threadIdx.x & 31;
    if (n >= Nn) return;
    float g = d_H[n * 64 + lane] * gW[lane] + d_H[n * 64 + 32 + lane] * gW[32 + lane];
    #pragma unroll
    for (int o = 16; o; o >>= 1) g += __shfl_xor_sync(0xffffffffu, g, o);
    g += gb[0];
    if (lane == 0) {
        d_GATE[n] = g;
        atomicMax(&d_GKEY[batch[n]], fkey(g));
    }
}

__global__ void k_gexp(const int* __restrict__ batch) {
    int n = blockIdx.x * blockDim.x + threadIdx.x;
    if (n >= Nn) return;
    int b = batch[n];
    float p = __expf(d_GATE[n] - fdecode(d_GKEY[b]));
    d_GP[n] = p;
    atomicAdd(&d_GDEN[b], p);
}

__global__ void k_gacc(const int* __restrict__ batch) {
    int i = blockIdx.x * blockDim.x + threadIdx.x;
    if (i >= Nn * OUTd) return;
    int n = i >> 5, c = i & 31;
    atomicAdd(&d_OSUM[batch[n] * OUTd + c], d_GP[n] * d_Y[i]);
}

__global__ void k_final(float* __restrict__ out) {
    int i = blockIdx.x * blockDim.x + threadIdx.x;
    if (i >= Gg * OUTd) return;
    float den = d_GDEN[i >> 5];
    out[i] = (den > 0.f) ? d_OSUM[i] / den : 0.f;
}

// ---------------- launch ----------------
extern "C" void kernel_launch(void* const* d_in, const int* in_sizes, int n_in,
                              void* d_out, int out_size) {
    const int*   x        = (const int*)d_in[0];
    const int*   ei       = (const int*)d_in[1];   // [2,E]: src = ei, dst = ei+E
    const int*   ea       = (const int*)d_in[2];
    const int*   batch    = (const int*)d_in[3];
    const float* node_emb = (const float*)d_in[4];
    const float* edge_emb = (const float*)d_in[5];
    const float* Wq       = (const float*)d_in[6];
    const float* Wk       = (const float*)d_in[7];
    const float* Wv       = (const float*)d_in[8];
    const float* We       = (const float*)d_in[9];
    const float* Wskip    = (const float*)d_in[10];
    const float* bq       = (const float*)d_in[11];
    const float* bk       = (const float*)d_in[12];
    const float* bv       = (const float*)d_in[13];
    const float* bskip    = (const float*)d_in[14];
    const float* gate_W   = (const float*)d_in[15];
    const float* gate_b   = (const float*)d_in[16];
    const float* out_W    = (const float*)d_in[17];
    const float* out_b    = (const float*)d_in[18];
    float* out = (float*)d_out;

    const int* srcp = ei;
    const int* dstp = ei + Ee;

    static bool attr_set = false;
    if (!attr_set) {
        cudaFuncSetAttribute(k_gemm, cudaFuncAttributeMaxDynamicSharedMemorySize, 74752);
        attr_set = true;
    }

    // init scratch
    k_init<<<(Nn + 255) / 256, 256>>>();
    // node embedding
    k_embed<<<(Nn * 64 + 255) / 256, 256>>>(x, node_emb);
    // CSR by dst
    k_hist<<<(Ee + 255) / 256, 256>>>(dstp);
    k_scan<<<1, 1024>>>();
    k_scatter<<<(Ee + 255) / 256, 256>>>(dstp);

    for (int l = 0; l < Ll; l++) {
        k_etab<<<1, 640>>>(edge_emb, We, l);
        k_gemm<<<(Nn + 31) / 32, 256, 74752>>>(Wq, Wk, Wv, Wskip, bq, bk, bv, bskip, l);
        k_edge<<<(Nn * 32 + 255) / 256, 256>>>(srcp, ea);
    }

    k_y<<<(Nn + 7) / 8, 256>>>(out_W, out_b);
    k_gate<<<(Nn * 32 + 255) / 256, 256>>>(gate_W, gate_b, batch);
    k_gexp<<<(Nn + 255) / 256, 256>>>(batch);
    k_gacc<<<(Nn * OUTd + 255) / 256, 256>>>(batch);
    k_final<<<(Gg * OUTd + 255) / 256, 256>>>(out);
}

// round 2
// speedup vs baseline: 1.2179x; 1.2179x over previous
#include <cuda_runtime.h>
#include <cuda_bf16.h>
#include <math_constants.h>

#define Nn 50000
#define Ee 800000
#define Hh 64
#define EDd 32
#define Ll 3
#define Gg 256
#define OUTd 32
#define NB 49   // ceil(Nn/1024)

// ---------------- static device scratch ----------------
__device__ float d_QKVS[Nn * 256];   // per-layer q|k|v|skip, 64 cols each
__device__ float d_H[Nn * 64];       // node features
__device__ float d_ALPHA[Ee];        // per-edge logits -> exp weights
__device__ int   d_CNT[Nn];
__device__ int   d_CUR[Nn];
__device__ int   d_OFF[Nn + 1];
__device__ int   d_BT[64];           // scan block totals
__device__ int   d_EID[Ee];          // edge ids sorted by dst (CSR)
__device__ float d_ET[Ll * 640];     // per-layer edge-type tables (10 types x 64)
__device__ unsigned d_GKEY[Gg];
__device__ float d_GDEN[Gg];
__device__ float d_OSUM[Gg * OUTd];
__device__ float d_GATE[Nn];
__device__ float d_GP[Nn];
__device__ float d_Y[Nn * OUTd];

// ---------------- helpers ----------------
__device__ __forceinline__ unsigned fkey(float f) {
    unsigned u = __float_as_uint(f);
    return (u & 0x80000000u) ? ~u : (u | 0x80000000u);
}
__device__ __forceinline__ float fdecode(unsigned k) {
    return (k & 0x80000000u) ? __uint_as_float(k & 0x7fffffffu) : __uint_as_float(~k);
}

// ---------------- init / zero ----------------
__global__ void k_init() {
    int i = blockIdx.x * blockDim.x + threadIdx.x;
    if (i < Nn) { d_CNT[i] = 0; d_CUR[i] = 0; }
    if (i < Gg) { d_GKEY[i] = 0u; d_GDEN[i] = 0.f; }
    if (i < Gg * OUTd) d_OSUM[i] = 0.f;
}

// ---------------- node embedding ----------------
__global__ void k_embed(const int* __restrict__ x, const float* __restrict__ node_emb) {
    int i = blockIdx.x * blockDim.x + threadIdx.x;
    if (i >= Nn * 64) return;
    int n = i >> 6, c = i & 63;
    d_H[i] = node_emb[x[n] * 64 + c];
}

// ---------------- CSR build ----------------
__global__ void k_hist(const int* __restrict__ dst) {
    int e = blockIdx.x * blockDim.x + threadIdx.x;
    if (e < Ee) atomicAdd(&d_CNT[dst[e]], 1);
}

// phase 1: per-block exclusive scan + block totals
__global__ void k_scan1() {
    __shared__ int wsum[32];
    int t = threadIdx.x, b = blockIdx.x;
    int i = b * 1024 + t;
    int v = (i < Nn) ? d_CNT[i] : 0;
    int lane = t & 31, w = t >> 5;
    int x = v;
    #pragma unroll
    for (int o = 1; o < 32; o <<= 1) {
        int y = __shfl_up_sync(0xffffffffu, x, o);
        if (lane >= o) x += y;
    }
    if (lane == 31) wsum[w] = x;
    __syncthreads();
    if (w == 0) {
        int s = wsum[lane];
        #pragma unroll
        for (int o = 1; o < 32; o <<= 1) {
            int y = __shfl_up_sync(0xffffffffu, s, o);
            if (lane >= o) s += y;
        }
        wsum[lane] = s;
    }
    __syncthreads();
    int excl = x - v + (w ? wsum[w - 1] : 0);
    if (i < Nn) d_OFF[i] = excl;
    if (t == 1023) d_BT[b] = excl + v;
}

// phase 2: scan the 49 block totals (trivial)
__global__ void k_scan2() {
    if (threadIdx.x == 0) {
        int s = 0;
        for (int b = 0; b < NB; b++) { int v = d_BT[b]; d_BT[b] = s; s += v; }
        d_OFF[Nn] = s;
    }
}

// phase 3: add block bases
__global__ void k_scan3() {
    int i = blockIdx.x * blockDim.x + threadIdx.x;
    if (i < Nn) d_OFF[i] += d_BT[i >> 10];
}

__global__ void k_scatter(const int* __restrict__ dst) {
    int e = blockIdx.x * blockDim.x + threadIdx.x;
    if (e >= Ee) return;
    int d = dst[e];
    int p = atomicAdd(&d_CUR[d], 1);
    d_EID[d_OFF[d] + p] = e;
}

// ---------------- all layers' edge-type tables: ET[l][type] = edge_emb[type] @ We[l] ----------------
__global__ void k_etab(const float* __restrict__ edge_emb, const float* __restrict__ We) {
    int t = threadIdx.x;                 // 640 threads, blockIdx = layer
    int l = blockIdx.x;
    if (t >= 640) return;
    int ty = t >> 6, c = t & 63;
    const float* W = We + l * (EDd * 64);
    float s = 0.f;
    #pragma unroll
    for (int j = 0; j < EDd; j++) s += edge_emb[ty * EDd + j] * W[j * 64 + c];
    d_ET[l * 640 + t] = s;
}

// ---------------- fused q,k,v,skip GEMM: QKVS = H @ [Wq|Wk|Wv|Wskip] + b ----------------
__global__ void k_gemm(const float* __restrict__ Wq, const float* __restrict__ Wk,
                       const float* __restrict__ Wv, const float* __restrict__ Ws,
                       const float* __restrict__ bq, const float* __restrict__ bk,
                       const float* __restrict__ bv, const float* __restrict__ bs, int l) {
    extern __shared__ float smem[];
    float* Wc = smem;              // 16384 floats
    float* bc = smem + 16384;      // 256
    float* hs = smem + 16640;      // 2048
    int t = threadIdx.x;

    for (int m = 0; m < 4; m++) {
        const float* W = (m == 0 ? Wq : m == 1 ? Wk : m == 2 ? Wv : Ws) + l * 4096;
        for (int i = t; i < 4096; i += 256) {
            int kk = i >> 6, cc = i & 63;
            Wc[kk * 256 + m * 64 + cc] = W[kk * 64 + cc];
        }
    }
    {
        const float* B = (t < 64) ? bq : (t < 128) ? bk : (t < 192) ? bv : bs;
        bc[t] = B[l * 64 + (t & 63)];
    }
    int node0 = blockIdx.x * 32;
    for (int i = t; i < 32 * 64; i += 256) {
        int n = i >> 6, kk = i & 63;
        int gn = node0 + n;
        hs[i] = (gn < Nn) ? d_H[gn * 64 + kk] : 0.f;
    }
    __syncthreads();

    int lane = t & 31, warp = t >> 5;
    float acc[4][8];
    #pragma unroll
    for (int i = 0; i < 4; i++)
        #pragma unroll
        for (int j = 0; j < 8; j++) acc[i][j] = 0.f;

    #pragma unroll 8
    for (int kk = 0; kk < 64; kk++) {
        float hv[4];
        #pragma unroll
        for (int i = 0; i < 4; i++) hv[i] = hs[(warp * 4 + i) * 64 + kk];
        #pragma unroll
        for (int j = 0; j < 8; j++) {
            float wv = Wc[kk * 256 + lane + 32 * j];
            #pragma unroll
            for (int i = 0; i < 4; i++) acc[i][j] += hv[i] * wv;
        }
    }
    #pragma unroll
    for (int i = 0; i < 4; i++) {
        int gn = node0 + warp * 4 + i;
        if (gn < Nn) {
            #pragma unroll
            for (int j = 0; j < 8; j++) {
                int c = lane + 32 * j;
                d_QKVS[gn * 256 + c] = acc[i][j] + bc[c];
            }
        }
    }
}

// ---------------- fused edge pass: warp per dst node, 4 edge-groups of 8 lanes ----------------
__global__ void k_edge(const int* __restrict__ src, const int* __restrict__ attr, int l) {
    __shared__ float et[640];
    for (int i = threadIdx.x; i < 640; i += blockDim.x) et[i] = d_ET[l * 640 + i];
    __syncthreads();

    int n = (blockIdx.x * blockDim.x + threadIdx.x) >> 5;
    int lane = threadIdx.x & 31;
    if (n >= Nn) return;
    int g = lane >> 3, r = lane & 7;
    unsigned gmask = 0xffu << (g * 8);
    int s0 = d_OFF[n], s1 = d_OFF[n + 1];

    // q columns r*8 .. r*8+7 (replicated across the 4 groups)
    float4 q0 = *(const float4*)&d_QKVS[n * 256 + r * 8];
    float4 q1 = *(const float4*)&d_QKVS[n * 256 + r * 8 + 4];

    // pass 1: logits, group-strided (4 edges in flight per warp)
    float mx = -CUDART_INF_F;
    for (int i = s0 + g; i < s1; i += 4) {
        int e = d_EID[i];
        int s = src[e], ty = attr[e];
        float4 k0 = *(const float4*)&d_QKVS[s * 256 + 64 + r * 8];
        float4 k1 = *(const float4*)&d_QKVS[s * 256 + 64 + r * 8 + 4];
        float4 e0 = *(const float4*)&et[ty * 64 + r * 8];
        float4 e1 = *(const float4*)&et[ty * 64 + r * 8 + 4];
        float d = q0.x * (k0.x + e0.x) + q0.y * (k0.y + e0.y)
                + q0.z * (k0.z + e0.z) + q0.w * (k0.w + e0.w)
                + q1.x * (k1.x + e1.x) + q1.y * (k1.y + e1.y)
                + q1.z * (k1.z + e1.z) + q1.w * (k1.w + e1.w);
        d += __shfl_xor_sync(gmask, d, 1);
        d += __shfl_xor_sync(gmask, d, 2);
        d += __shfl_xor_sync(gmask, d, 4);
        d *= 0.125f;
        if (r == 0) d_ALPHA[e] = d;
        mx = fmaxf(mx, d);
    }
    // combine group maxima (warp fully converged here)
    mx = fmaxf(mx, __shfl_xor_sync(0xffffffffu, mx, 8));
    mx = fmaxf(mx, __shfl_xor_sync(0xffffffffu, mx, 16));
    __syncwarp();
    __threadfence_block();

    // pass 2: exp + sum (lane-strided, one exp per edge)
    float sum = 0.f;
    for (int i = s0 + lane; i < s1; i += 32) {
        int e = d_EID[i];
        float p = __expf(d_ALPHA[e] - mx);
        d_ALPHA[e] = p;
        sum += p;
    }
    #pragma unroll
    for (int o = 16; o; o >>= 1) sum += __shfl_xor_sync(0xffffffffu, sum, o);
    __syncwarp();
    __threadfence_block();
    float inv = (s1 > s0) ? 1.f / sum : 0.f;

    // pass 3: weighted aggregation, group-strided, register accumulators
    float a[8];
    #pragma unroll
    for (int c = 0; c < 8; c++) a[c] = 0.f;
    for (int i = s0 + g; i < s1; i += 4) {
        int e = d_EID[i];
        int s = src[e], ty = attr[e];
        float p = d_ALPHA[e];
        float4 v0 = *(const float4*)&d_QKVS[s * 256 + 128 + r * 8];
        float4 v1 = *(const float4*)&d_QKVS[s * 256 + 128 + r * 8 + 4];
        float4 e0 = *(const float4*)&et[ty * 64 + r * 8];
        float4 e1 = *(const float4*)&et[ty * 64 + r * 8 + 4];
        a[0] += (v0.x + e0.x) * p; a[1] += (v0.y + e0.y) * p;
        a[2] += (v0.z + e0.z) * p; a[3] += (v0.w + e0.w) * p;
        a[4] += (v1.x + e1.x) * p; a[5] += (v1.y + e1.y) * p;
        a[6] += (v1.z + e1.z) * p; a[7] += (v1.w + e1.w) * p;
    }
    // sum across the 4 groups: lane (g,r) holds cols r*8..+7
    #pragma unroll
    for (int c = 0; c < 8; c++) {
        a[c] += __shfl_xor_sync(0xffffffffu, a[c], 8);
        a[c] += __shfl_xor_sync(0xffffffffu, a[c], 16);
    }
    if (g == 0) {
        float4 sk0 = *(const float4*)&d_QKVS[n * 256 + 192 + r * 8];
        float4 sk1 = *(const float4*)&d_QKVS[n * 256 + 192 + r * 8 + 4];
        float4 o0, o1;
        o0.x = fmaxf(a[0] * inv + sk0.x, 0.f);
        o0.y = fmaxf(a[1] * inv + sk0.y, 0.f);
        o0.z = fmaxf(a[2] * inv + sk0.z, 0.f);
        o0.w = fmaxf(a[3] * inv + sk0.w, 0.f);
        o1.x = fmaxf(a[4] * inv + sk1.x, 0.f);
        o1.y = fmaxf(a[5] * inv + sk1.y, 0.f);
        o1.z = fmaxf(a[6] * inv + sk1.z, 0.f);
        o1.w = fmaxf(a[7] * inv + sk1.w, 0.f);
        *(float4*)&d_H[n * 64 + r * 8] = o0;
        *(float4*)&d_H[n * 64 + r * 8 + 4] = o1;
    }
}

// ---------------- readout ----------------
__global__ void k_y(const float* __restrict__ out_W, const float* __restrict__ out_b) {
    __shared__ float Wm[64 * OUTd];
    __shared__ float bb[OUTd];
    for (int i = threadIdx.x; i < 64 * OUTd; i += 256) Wm[i] = out_W[i];
    if (threadIdx.x < OUTd) bb[threadIdx.x] = out_b[threadIdx.x];
    __syncthreads();
    int n = blockIdx.x * 8 + (threadIdx.x >> 5);
    int c = threadIdx.x & 31;
    if (n >= Nn) return;
    float s = bb[c];
    #pragma unroll 8
    for (int kk = 0; kk < 64; kk++) s += d_H[n * 64 + kk] * Wm[kk * OUTd + c];
    d_Y[n * OUTd + c] = s;
}

__global__ void k_gate(const float* __restrict__ gW, const float* __restrict__ gb,
                       const int* __restrict__ batch) {
    int n = (blockIdx.x * blockDim.x + threadIdx.x) >> 5;
    int lane = threadIdx.x & 31;
    if (n >= Nn) return;
    float g = d_H[n * 64 + lane] * gW[lane] + d_H[n * 64 + 32 + lane] * gW[32 + lane];
    #pragma unroll
    for (int o = 16; o; o >>= 1) g += __shfl_xor_sync(0xffffffffu, g, o);
    g += gb[0];
    if (lane == 0) {
        d_GATE[n] = g;
        atomicMax(&d_GKEY[batch[n]], fkey(g));
    }
}

__global__ void k_gexp(const int* __restrict__ batch) {
    int n = blockIdx.x * blockDim.x + threadIdx.x;
    if (n >= Nn) return;
    int b = batch[n];
    float p = __expf(d_GATE[n] - fdecode(d_GKEY[b]));
    d_GP[n] = p;
    atomicAdd(&d_GDEN[b], p);
}

__global__ void k_gacc(const int* __restrict__ batch) {
    int i = blockIdx.x * blockDim.x + threadIdx.x;
    if (i >= Nn * OUTd) return;
    int n = i >> 5, c = i & 31;
    atomicAdd(&d_OSUM[batch[n] * OUTd + c], d_GP[n] * d_Y[i]);
}

__global__ void k_final(float* __restrict__ out) {
    int i = blockIdx.x * blockDim.x + threadIdx.x;
    if (i >= Gg * OUTd) return;
    float den = d_GDEN[i >> 5];
    out[i] = (den > 0.f) ? d_OSUM[i] / den : 0.f;
}

// ---------------- launch ----------------
extern "C" void kernel_launch(void* const* d_in, const int* in_sizes, int n_in,
                              void* d_out, int out_size) {
    const int*   x        = (const int*)d_in[0];
    const int*   ei       = (const int*)d_in[1];
    const int*   ea       = (const int*)d_in[2];
    const int*   batch    = (const int*)d_in[3];
    const float* node_emb = (const float*)d_in[4];
    const float* edge_emb = (const float*)d_in[5];
    const float* Wq       = (const float*)d_in[6];
    const float* Wk       = (const float*)d_in[7];
    const float* Wv       = (const float*)d_in[8];
    const float* We       = (const float*)d_in[9];
    const float* Wskip    = (const float*)d_in[10];
    const float* bq       = (const float*)d_in[11];
    const float* bk       = (const float*)d_in[12];
    const float* bv       = (const float*)d_in[13];
    const float* bskip    = (const float*)d_in[14];
    const float* gate_W   = (const float*)d_in[15];
    const float* gate_b   = (const float*)d_in[16];
    const float* out_W    = (const float*)d_in[17];
    const float* out_b    = (const float*)d_in[18];
    float* out = (float*)d_out;

    const int* srcp = ei;
    const int* dstp = ei + Ee;

    static bool attr_set = false;
    if (!attr_set) {
        cudaFuncSetAttribute(k_gemm, cudaFuncAttributeMaxDynamicSharedMemorySize, 74752);
        attr_set = true;
    }

    k_init<<<(Nn + 255) / 256, 256>>>();
    k_embed<<<(Nn * 64 + 255) / 256, 256>>>(x, node_emb);
    k_hist<<<(Ee + 255) / 256, 256>>>(dstp);
    k_scan1<<<NB, 1024>>>();
    k_scan2<<<1, 32>>>();
    k_scan3<<<(Nn + 255) / 256, 256>>>();
    k_scatter<<<(Ee + 255) / 256, 256>>>(dstp);
    k_etab<<<Ll, 640>>>(edge_emb, We);

    for (int l = 0; l < Ll; l++) {
        k_gemm<<<(Nn + 31) / 32, 256, 74752>>>(Wq, Wk, Wv, Wskip, bq, bk, bv, bskip, l);
        k_edge<<<(Nn * 32 + 255) / 256, 256>>>(srcp, ea, l);
    }

    k_y<<<(Nn + 7) / 8, 256>>>(out_W, out_b);
    k_gate<<<(Nn * 32 + 255) / 256, 256>>>(gate_W, gate_b, batch);
    k_gexp<<<(Nn + 255) / 256, 256>>>(batch);
    k_gacc<<<(Nn * OUTd + 255) / 256, 256>>>(batch);
    k_final<<<(Gg * OUTd + 255) / 256, 256>>>(out);
}

// round 3
// speedup vs baseline: 1.6342x; 1.3419x over previous
#include <cuda_runtime.h>
#include <cuda_bf16.h>
#include <math_constants.h>

#define Nn 50000
#define Ee 800000
#define Hh 64
#define EDd 32
#define Ll 3
#define Gg 256
#define OUTd 32
#define NB 49   // ceil(Nn/1024)

// ---------------- static device scratch ----------------
__device__ float d_QKVS[Nn * 256];   // per-layer q|k|v|skip, 64 cols each
__device__ float d_H[Nn * 64];       // node features
__device__ int   d_CNT[Nn];
__device__ int   d_CUR[Nn];
__device__ int   d_OFF[Nn + 1];
__device__ int   d_BT[64];           // scan block totals
__device__ unsigned d_EPK[Ee];       // CSR slots: src | (attr<<16)
__device__ float d_ET[Ll * 640];     // per-layer edge-type tables (10 types x 64)
__device__ unsigned d_GKEY[Gg];
__device__ float d_GDEN[Gg];
__device__ float d_OSUM[Gg * OUTd];
__device__ float d_GATE[Nn];
__device__ float d_GP[Nn];
__device__ float d_Y[Nn * OUTd];

// ---------------- helpers ----------------
__device__ __forceinline__ unsigned fkey(float f) {
    unsigned u = __float_as_uint(f);
    return (u & 0x80000000u) ? ~u : (u | 0x80000000u);
}
__device__ __forceinline__ float fdecode(unsigned k) {
    return (k & 0x80000000u) ? __uint_as_float(k & 0x7fffffffu) : __uint_as_float(~k);
}
__device__ __forceinline__ unsigned long long pk2(float lo, float hi) {
    unsigned long long r;
    asm("mov.b64 %0, {%1, %2};" : "=l"(r) : "f"(lo), "f"(hi));
    return r;
}
__device__ __forceinline__ void upk2(float& lo, float& hi, unsigned long long v) {
    asm("mov.b64 {%0, %1}, %2;" : "=f"(lo), "=f"(hi) : "l"(v));
}
__device__ __forceinline__ void ffma2(unsigned long long& acc, unsigned long long a,
                                      unsigned long long b) {
    asm("fma.rn.f32x2 %0, %1, %2, %0;" : "+l"(acc) : "l"(a), "l"(b));
}

// ---------------- init / zero ----------------
__global__ void k_init() {
    int i = blockIdx.x * blockDim.x + threadIdx.x;
    if (i < Nn) { d_CNT[i] = 0; d_CUR[i] = 0; }
    if (i < Gg) { d_GKEY[i] = 0u; d_GDEN[i] = 0.f; }
    if (i < Gg * OUTd) d_OSUM[i] = 0.f;
}

// ---------------- node embedding ----------------
__global__ void k_embed(const int* __restrict__ x, const float* __restrict__ node_emb) {
    int i = blockIdx.x * blockDim.x + threadIdx.x;
    if (i >= Nn * 64) return;
    int n = i >> 6, c = i & 63;
    d_H[i] = node_emb[x[n] * 64 + c];
}

// ---------------- CSR build ----------------
__global__ void k_hist(const int* __restrict__ dst) {
    int e = blockIdx.x * blockDim.x + threadIdx.x;
    if (e < Ee) atomicAdd(&d_CNT[dst[e]], 1);
}

__global__ void k_scan1() {
    __shared__ int wsum[32];
    int t = threadIdx.x, b = blockIdx.x;
    int i = b * 1024 + t;
    int v = (i < Nn) ? d_CNT[i] : 0;
    int lane = t & 31, w = t >> 5;
    int x = v;
    #pragma unroll
    for (int o = 1; o < 32; o <<= 1) {
        int y = __shfl_up_sync(0xffffffffu, x, o);
        if (lane >= o) x += y;
    }
    if (lane == 31) wsum[w] = x;
    __syncthreads();
    if (w == 0) {
        int s = wsum[lane];
        #pragma unroll
        for (int o = 1; o < 32; o <<= 1) {
            int y = __shfl_up_sync(0xffffffffu, s, o);
            if (lane >= o) s += y;
        }
        wsum[lane] = s;
    }
    __syncthreads();
    int excl = x - v + (w ? wsum[w - 1] : 0);
    if (i < Nn) d_OFF[i] = excl;
    if (t == 1023) d_BT[b] = excl + v;
}

__global__ void k_scan2() {
    if (threadIdx.x == 0) {
        int s = 0;
        for (int b = 0; b < NB; b++) { int v = d_BT[b]; d_BT[b] = s; s += v; }
        d_OFF[Nn] = s;
    }
}

__global__ void k_scan3() {
    int i = blockIdx.x * blockDim.x + threadIdx.x;
    if (i < Nn) d_OFF[i] += d_BT[i >> 10];
}

// scatter packed (src | attr<<16) into CSR slots
__global__ void k_scatter(const int* __restrict__ src, const int* __restrict__ dst,
                          const int* __restrict__ attr) {
    int e = blockIdx.x * blockDim.x + threadIdx.x;
    if (e >= Ee) return;
    int d = dst[e];
    int p = atomicAdd(&d_CUR[d], 1);
    d_EPK[d_OFF[d] + p] = (unsigned)src[e] | ((unsigned)attr[e] << 16);
}

// ---------------- edge-type tables ----------------
__global__ void k_etab(const float* __restrict__ edge_emb, const float* __restrict__ We) {
    int t = threadIdx.x;                 // 640 threads, blockIdx = layer
    int l = blockIdx.x;
    if (t >= 640) return;
    int ty = t >> 6, c = t & 63;
    const float* W = We + l * (EDd * 64);
    float s = 0.f;
    #pragma unroll
    for (int j = 0; j < EDd; j++) s += edge_emb[ty * EDd + j] * W[j * 64 + c];
    d_ET[l * 640 + t] = s;
}

// ---------------- fused q,k,v,skip GEMM with packed f32x2 FFMA ----------------
// block: 256 threads, 32 nodes x 256 cols. lane owns col pairs (64j + 2*lane).
__global__ void k_gemm(const float* __restrict__ Wq, const float* __restrict__ Wk,
                       const float* __restrict__ Wv, const float* __restrict__ Ws,
                       const float* __restrict__ bq, const float* __restrict__ bk,
                       const float* __restrict__ bv, const float* __restrict__ bs, int l) {
    extern __shared__ float smem[];
    float* Wc = smem;              // 16384 floats: [k][256]
    float* bc = smem + 16384;      // 256
    float* hs = smem + 16640;      // 2048
    int t = threadIdx.x;

    for (int m = 0; m < 4; m++) {
        const float* W = (m == 0 ? Wq : m == 1 ? Wk : m == 2 ? Wv : Ws) + l * 4096;
        for (int i = t; i < 4096; i += 256) {
            int kk = i >> 6, cc = i & 63;
            Wc[kk * 256 + m * 64 + cc] = W[kk * 64 + cc];
        }
    }
    {
        const float* B = (t < 64) ? bq : (t < 128) ? bk : (t < 192) ? bv : bs;
        bc[t] = B[l * 64 + (t & 63)];
    }
    int node0 = blockIdx.x * 32;
    for (int i = t; i < 32 * 64; i += 256) {
        int n = i >> 6, kk = i & 63;
        int gn = node0 + n;
        hs[i] = (gn < Nn) ? d_H[gn * 64 + kk] : 0.f;
    }
    __syncthreads();

    int lane = t & 31, warp = t >> 5;
    unsigned long long acc[4][4];
    #pragma unroll
    for (int i = 0; i < 4; i++)
        #pragma unroll
        for (int j = 0; j < 4; j++) acc[i][j] = 0ull;

    #pragma unroll 8
    for (int kk = 0; kk < 64; kk++) {
        unsigned long long hp[4];
        #pragma unroll
        for (int i = 0; i < 4; i++) {
            float hv = hs[(warp * 4 + i) * 64 + kk];   // broadcast
            hp[i] = pk2(hv, hv);
        }
        #pragma unroll
        for (int j = 0; j < 4; j++) {
            unsigned long long wv =
                *(const unsigned long long*)&Wc[kk * 256 + j * 64 + 2 * lane];
            #pragma unroll
            for (int i = 0; i < 4; i++) ffma2(acc[i][j], hp[i], wv);
        }
    }
    #pragma unroll
    for (int i = 0; i < 4; i++) {
        int gn = node0 + warp * 4 + i;
        if (gn < Nn) {
            #pragma unroll
            for (int j = 0; j < 4; j++) {
                int c = j * 64 + 2 * lane;
                float lo, hi;
                upk2(lo, hi, acc[i][j]);
                float2 o;
                o.x = lo + bc[c];
                o.y = hi + bc[c + 1];
                *(float2*)&d_QKVS[gn * 256 + c] = o;
            }
        }
    }
}

// ---------------- single-pass edge kernel: online softmax + aggregation ----------------
// warp per dst node; 4 groups of 8 lanes, each group owns one edge at a time.
__global__ void k_edge(int l) {
    __shared__ float et[640];
    for (int i = threadIdx.x; i < 640; i += blockDim.x) et[i] = d_ET[l * 640 + i];
    __syncthreads();

    int n = (blockIdx.x * blockDim.x + threadIdx.x) >> 5;
    int lane = threadIdx.x & 31;
    if (n >= Nn) return;
    int g = lane >> 3, r = lane & 7;
    unsigned gmask = 0xffu << (g * 8);
    int s0 = d_OFF[n], s1 = d_OFF[n + 1];

    if (s0 == s1) {          // isolated node: h = relu(skip)
        if (g == 0) {
            float4 sk0 = *(const float4*)&d_QKVS[n * 256 + 192 + r * 8];
            float4 sk1 = *(const float4*)&d_QKVS[n * 256 + 192 + r * 8 + 4];
            float4 o0, o1;
            o0.x = fmaxf(sk0.x, 0.f); o0.y = fmaxf(sk0.y, 0.f);
            o0.z = fmaxf(sk0.z, 0.f); o0.w = fmaxf(sk0.w, 0.f);
            o1.x = fmaxf(sk1.x, 0.f); o1.y = fmaxf(sk1.y, 0.f);
            o1.z = fmaxf(sk1.z, 0.f); o1.w = fmaxf(sk1.w, 0.f);
            *(float4*)&d_H[n * 64 + r * 8] = o0;
            *(float4*)&d_H[n * 64 + r * 8 + 4] = o1;
        }
        return;
    }

    // q columns r*8 .. r*8+7 (replicated across the 4 groups)
    float4 q0 = *(const float4*)&d_QKVS[n * 256 + r * 8];
    float4 q1 = *(const float4*)&d_QKVS[n * 256 + r * 8 + 4];

    float m = -CUDART_INF_F, ssum = 0.f;
    float a[8];
    #pragma unroll
    for (int c = 0; c < 8; c++) a[c] = 0.f;

    for (int i = s0 + g; i < s1; i += 4) {
        unsigned pk = d_EPK[i];
        int s = pk & 0xffffu, ty = pk >> 16;
        const float* base = &d_QKVS[s * 256 + 64 + r * 8];
        float4 k0 = *(const float4*)(base);
        float4 k1 = *(const float4*)(base + 4);
        float4 v0 = *(const float4*)(base + 64);
        float4 v1 = *(const float4*)(base + 68);
        float4 e0 = *(const float4*)&et[ty * 64 + r * 8];
        float4 e1 = *(const float4*)&et[ty * 64 + r * 8 + 4];
        float d = q0.x * (k0.x + e0.x) + q0.y * (k0.y + e0.y)
                + q0.z * (k0.z + e0.z) + q0.w * (k0.w + e0.w)
                + q1.x * (k1.x + e1.x) + q1.y * (k1.y + e1.y)
                + q1.z * (k1.z + e1.z) + q1.w * (k1.w + e1.w);
        d += __shfl_xor_sync(gmask, d, 1);
        d += __shfl_xor_sync(gmask, d, 2);
        d += __shfl_xor_sync(gmask, d, 4);
        d *= 0.125f;
        float mn = fmaxf(m, d);
        float fac = __expf(m - mn);      // 1 if max unchanged; 0 on first edge
        float p = __expf(d - mn);
        ssum = ssum * fac + p;
        a[0] = a[0] * fac + p * (v0.x + e0.x);
        a[1] = a[1] * fac + p * (v0.y + e0.y);
        a[2] = a[2] * fac + p * (v0.z + e0.z);
        a[3] = a[3] * fac + p * (v0.w + e0.w);
        a[4] = a[4] * fac + p * (v1.x + e1.x);
        a[5] = a[5] * fac + p * (v1.y + e1.y);
        a[6] = a[6] * fac + p * (v1.z + e1.z);
        a[7] = a[7] * fac + p * (v1.w + e1.w);
        m = mn;
    }

    // combine the 4 groups (lanes differing in bits 3,4 of lane id are other groups)
    float M = fmaxf(m, __shfl_xor_sync(0xffffffffu, m, 8));
    M = fmaxf(M, __shfl_xor_sync(0xffffffffu, M, 16));
    float fac = __expf(m - M);           // 0 for empty groups (m = -inf)
    ssum *= fac;
    ssum += __shfl_xor_sync(0xffffffffu, ssum, 8);
    ssum += __shfl_xor_sync(0xffffffffu, ssum, 16);
    #pragma unroll
    for (int c = 0; c < 8; c++) {
        a[c] *= fac;
        a[c] += __shfl_xor_sync(0xffffffffu, a[c], 8);
        a[c] += __shfl_xor_sync(0xffffffffu, a[c], 16);
    }
    float inv = 1.f / ssum;

    if (g == 0) {
        float4 sk0 = *(const float4*)&d_QKVS[n * 256 + 192 + r * 8];
        float4 sk1 = *(const float4*)&d_QKVS[n * 256 + 192 + r * 8 + 4];
        float4 o0, o1;
        o0.x = fmaxf(a[0] * inv + sk0.x, 0.f);
        o0.y = fmaxf(a[1] * inv + sk0.y, 0.f);
        o0.z = fmaxf(a[2] * inv + sk0.z, 0.f);
        o0.w = fmaxf(a[3] * inv + sk0.w, 0.f);
        o1.x = fmaxf(a[4] * inv + sk1.x, 0.f);
        o1.y = fmaxf(a[5] * inv + sk1.y, 0.f);
        o1.z = fmaxf(a[6] * inv + sk1.z, 0.f);
        o1.w = fmaxf(a[7] * inv + sk1.w, 0.f);
        *(float4*)&d_H[n * 64 + r * 8] = o0;
        *(float4*)&d_H[n * 64 + r * 8 + 4] = o1;
    }
}

// ---------------- readout ----------------
__global__ void k_y(const float* __restrict__ out_W, const float* __restrict__ out_b) {
    __shared__ float Wm[64 * OUTd];
    __shared__ float bb[OUTd];
    for (int i = threadIdx.x; i < 64 * OUTd; i += 256) Wm[i] = out_W[i];
    if (threadIdx.x < OUTd) bb[threadIdx.x] = out_b[threadIdx.x];
    __syncthreads();
    int n = blockIdx.x * 8 + (threadIdx.x >> 5);
    int c = threadIdx.x & 31;
    if (n >= Nn) return;
    float s = bb[c];
    #pragma unroll 8
    for (int kk = 0; kk < 64; kk++) s += d_H[n * 64 + kk] * Wm[kk * OUTd + c];
    d_Y[n * OUTd + c] = s;
}

__global__ void k_gate(const float* __restrict__ gW, const float* __restrict__ gb,
                       const int* __restrict__ batch) {
    int n = (blockIdx.x * blockDim.x + threadIdx.x) >> 5;
    int lane = threadIdx.x & 31;
    if (n >= Nn) return;
    float g = d_H[n * 64 + lane] * gW[lane] + d_H[n * 64 + 32 + lane] * gW[32 + lane];
    #pragma unroll
    for (int o = 16; o; o >>= 1) g += __shfl_xor_sync(0xffffffffu, g, o);
    g += gb[0];
    if (lane == 0) {
        d_GATE[n] = g;
        atomicMax(&d_GKEY[batch[n]], fkey(g));
    }
}

__global__ void k_gexp(const int* __restrict__ batch) {
    int n = blockIdx.x * blockDim.x + threadIdx.x;
    if (n >= Nn) return;
    int b = batch[n];
    float p = __expf(d_GATE[n] - fdecode(d_GKEY[b]));
    d_GP[n] = p;
    atomicAdd(&d_GDEN[b], p);
}

__global__ void k_gacc(const int* __restrict__ batch) {
    int i = blockIdx.x * blockDim.x + threadIdx.x;
    if (i >= Nn * OUTd) return;
    int n = i >> 5, c = i & 31;
    atomicAdd(&d_OSUM[batch[n] * OUTd + c], d_GP[n] * d_Y[i]);
}

__global__ void k_final(float* __restrict__ out) {
    int i = blockIdx.x * blockDim.x + threadIdx.x;
    if (i >= Gg * OUTd) return;
    float den = d_GDEN[i >> 5];
    out[i] = (den > 0.f) ? d_OSUM[i] / den : 0.f;
}

// ---------------- launch ----------------
extern "C" void kernel_launch(void* const* d_in, const int* in_sizes, int n_in,
                              void* d_out, int out_size) {
    const int*   x        = (const int*)d_in[0];
    const int*   ei       = (const int*)d_in[1];
    const int*   ea       = (const int*)d_in[2];
    const int*   batch    = (const int*)d_in[3];
    const float* node_emb = (const float*)d_in[4];
    const float* edge_emb = (const float*)d_in[5];
    const float* Wq       = (const float*)d_in[6];
    const float* Wk       = (const float*)d_in[7];
    const float* Wv       = (const float*)d_in[8];
    const float* We       = (const float*)d_in[9];
    const float* Wskip    = (const float*)d_in[10];
    const float* bq       = (const float*)d_in[11];
    const float* bk       = (const float*)d_in[12];
    const float* bv       = (const float*)d_in[13];
    const float* bskip    = (const float*)d_in[14];
    const float* gate_W   = (const float*)d_in[15];
    const float* gate_b   = (const float*)d_in[16];
    const float* out_W    = (const float*)d_in[17];
    const float* out_b    = (const float*)d_in[18];
    float* out = (float*)d_out;

    const int* srcp = ei;
    const int* dstp = ei + Ee;

    static bool attr_set = false;
    if (!attr_set) {
        cudaFuncSetAttribute(k_gemm, cudaFuncAttributeMaxDynamicSharedMemorySize, 74752);
        attr_set = true;
    }

    k_init<<<(Nn + 255) / 256, 256>>>();
    k_embed<<<(Nn * 64 + 255) / 256, 256>>>(x, node_emb);
    k_hist<<<(Ee + 255) / 256, 256>>>(dstp);
    k_scan1<<<NB, 1024>>>();
    k_scan2<<<1, 32>>>();
    k_scan3<<<(Nn + 255) / 256, 256>>>();
    k_scatter<<<(Ee + 255) / 256, 256>>>(srcp, dstp, ea);
    k_etab<<<Ll, 640>>>(edge_emb, We);

    for (int l = 0; l < Ll; l++) {
        k_gemm<<<(Nn + 31) / 32, 256, 74752>>>(Wq, Wk, Wv, Wskip, bq, bk, bv, bskip, l);
        k_edge<<<(Nn * 32 + 255) / 256, 256>>>(l);
    }

    k_y<<<(Nn + 7) / 8, 256>>>(out_W, out_b);
    k_gate<<<(Nn * 32 + 255) / 256, 256>>>(gate_W, gate_b, batch);
    k_gexp<<<(Nn + 255) / 256, 256>>>(batch);
    k_gacc<<<(Nn * OUTd + 255) / 256, 256>>>(batch);
    k_final<<<(Gg * OUTd + 255) / 256, 256>>>(out);
}

// round 4
// speedup vs baseline: 1.6343x; 1.0001x over previous
#include <cuda_runtime.h>
#include <cuda_bf16.h>
#include <math_constants.h>

#define Nn 50000
#define Ee 800000
#define Hh 64
#define EDd 32
#define Ll 3
#define Gg 256
#define OUTd 32
#define NB 49   // ceil(Nn/1024)

// ---------------- static device scratch ----------------
__device__ float d_QKVS[Nn * 256];   // per-layer q|k|v|skip, 64 cols each
__device__ float d_H[Nn * 64];       // node features
__device__ int   d_CNT[Nn];          // zeroed by k_scan1 for next replay
__device__ int   d_CUR[Nn];          // zeroed by k_scan1 for next replay
__device__ int   d_OFF[Nn + 1];
__device__ int   d_BT[64];           // scan block totals
__device__ unsigned d_EPK[Ee];       // CSR slots: src | (attr<<16)
__device__ float d_ET[Ll * 640];     // per-layer edge-type tables (10 types x 64)
__device__ unsigned d_GKEY[Gg];
__device__ float d_GDEN[Gg];
__device__ float d_OSUM[Gg * OUTd];
__device__ float d_GATE[Nn];
__device__ float d_Y[Nn * OUTd];

// ---------------- helpers ----------------
__device__ __forceinline__ unsigned fkey(float f) {
    unsigned u = __float_as_uint(f);
    return (u & 0x80000000u) ? ~u : (u | 0x80000000u);
}
__device__ __forceinline__ float fdecode(unsigned k) {
    return (k & 0x80000000u) ? __uint_as_float(k & 0x7fffffffu) : __uint_as_float(~k);
}
__device__ __forceinline__ unsigned long long pk2(float lo, float hi) {
    unsigned long long r;
    asm("mov.b64 %0, {%1, %2};" : "=l"(r) : "f"(lo), "f"(hi));
    return r;
}
__device__ __forceinline__ void upk2(float& lo, float& hi, unsigned long long v) {
    asm("mov.b64 {%0, %1}, %2;" : "=f"(lo), "=f"(hi) : "l"(v));
}
__device__ __forceinline__ void ffma2(unsigned long long& acc, unsigned long long a,
                                      unsigned long long b) {
    asm("fma.rn.f32x2 %0, %1, %2, %0;" : "+l"(acc) : "l"(a), "l"(b));
}

// ---------------- prep: embed + hist + etab + zero readout scratch ----------------
__global__ void k_prep(const int* __restrict__ x, const float* __restrict__ node_emb,
                       const int* __restrict__ dst,
                       const float* __restrict__ edge_emb, const float* __restrict__ We) {
    int i = blockIdx.x * blockDim.x + threadIdx.x;
    if (i < Nn * 64) {
        int n = i >> 6, c = i & 63;
        d_H[i] = node_emb[x[n] * 64 + c];
    }
    if (i < Ee) atomicAdd(&d_CNT[dst[i]], 1);
    if (i < Ll * 640) {
        int l = i / 640, t = i % 640;
        int ty = t >> 6, c = t & 63;
        const float* W = We + l * (EDd * 64);
        float s = 0.f;
        #pragma unroll
        for (int j = 0; j < EDd; j++) s += edge_emb[ty * EDd + j] * W[j * 64 + c];
        d_ET[i] = s;
    }
    if (i < Gg) { d_GKEY[i] = 0u; d_GDEN[i] = 0.f; }
    if (i < Gg * OUTd) d_OSUM[i] = 0.f;
}

// ---------------- CSR scan (self-cleaning) ----------------
__global__ void k_scan1() {
    __shared__ int wsum[32];
    int t = threadIdx.x, b = blockIdx.x;
    int i = b * 1024 + t;
    int v = (i < Nn) ? d_CNT[i] : 0;
    int lane = t & 31, w = t >> 5;
    int x = v;
    #pragma unroll
    for (int o = 1; o < 32; o <<= 1) {
        int y = __shfl_up_sync(0xffffffffu, x, o);
        if (lane >= o) x += y;
    }
    if (lane == 31) wsum[w] = x;
    __syncthreads();
    if (w == 0) {
        int s = wsum[lane];
        #pragma unroll
        for (int o = 1; o < 32; o <<= 1) {
            int y = __shfl_up_sync(0xffffffffu, s, o);
            if (lane >= o) s += y;
        }
        wsum[lane] = s;
    }
    __syncthreads();
    int excl = x - v + (w ? wsum[w - 1] : 0);
    if (i < Nn) {
        d_OFF[i] = excl;
        d_CNT[i] = 0;      // ready for next replay
        d_CUR[i] = 0;
    }
    if (t == 1023) d_BT[b] = excl + v;
}

__global__ void k_scan2() {
    if (threadIdx.x == 0) {
        int s = 0;
        for (int b = 0; b < NB; b++) { int v = d_BT[b]; d_BT[b] = s; s += v; }
        d_OFF[Nn] = s;
    }
}

__global__ void k_scan3() {
    int i = blockIdx.x * blockDim.x + threadIdx.x;
    if (i < Nn) d_OFF[i] += d_BT[i >> 10];
}

__global__ void k_scatter(const int* __restrict__ src, const int* __restrict__ dst,
                          const int* __restrict__ attr) {
    int e = blockIdx.x * blockDim.x + threadIdx.x;
    if (e >= Ee) return;
    int d = dst[e];
    int p = atomicAdd(&d_CUR[d], 1);
    d_EPK[d_OFF[d] + p] = (unsigned)src[e] | ((unsigned)attr[e] << 16);
}

// ---------------- fused q,k,v,skip GEMM with packed f32x2 FFMA ----------------
__global__ void k_gemm(const float* __restrict__ Wq, const float* __restrict__ Wk,
                       const float* __restrict__ Wv, const float* __restrict__ Ws,
                       const float* __restrict__ bq, const float* __restrict__ bk,
                       const float* __restrict__ bv, const float* __restrict__ bs, int l) {
    extern __shared__ float smem[];
    float* Wc = smem;              // 16384 floats: [k][256]
    float* bc = smem + 16384;      // 256
    float* hs = smem + 16640;      // 2048
    int t = threadIdx.x;

    for (int m = 0; m < 4; m++) {
        const float* W = (m == 0 ? Wq : m == 1 ? Wk : m == 2 ? Wv : Ws) + l * 4096;
        for (int i = t; i < 4096; i += 256) {
            int kk = i >> 6, cc = i & 63;
            Wc[kk * 256 + m * 64 + cc] = W[kk * 64 + cc];
        }
    }
    {
        const float* B = (t < 64) ? bq : (t < 128) ? bk : (t < 192) ? bv : bs;
        bc[t] = B[l * 64 + (t & 63)];
    }
    int node0 = blockIdx.x * 32;
    for (int i = t; i < 32 * 64; i += 256) {
        int n = i >> 6, kk = i & 63;
        int gn = node0 + n;
        hs[i] = (gn < Nn) ? __ldg(&d_H[gn * 64 + kk]) : 0.f;
    }
    __syncthreads();

    int lane = t & 31, warp = t >> 5;
    unsigned long long acc[4][4];
    #pragma unroll
    for (int i = 0; i < 4; i++)
        #pragma unroll
        for (int j = 0; j < 4; j++) acc[i][j] = 0ull;

    #pragma unroll 8
    for (int kk = 0; kk < 64; kk++) {
        unsigned long long hp[4];
        #pragma unroll
        for (int i = 0; i < 4; i++) {
            float hv = hs[(warp * 4 + i) * 64 + kk];
            hp[i] = pk2(hv, hv);
        }
        #pragma unroll
        for (int j = 0; j < 4; j++) {
            unsigned long long wv =
                *(const unsigned long long*)&Wc[kk * 256 + j * 64 + 2 * lane];
            #pragma unroll
            for (int i = 0; i < 4; i++) ffma2(acc[i][j], hp[i], wv);
        }
    }
    #pragma unroll
    for (int i = 0; i < 4; i++) {
        int gn = node0 + warp * 4 + i;
        if (gn < Nn) {
            #pragma unroll
            for (int j = 0; j < 4; j++) {
                int c = j * 64 + 2 * lane;
                float lo, hi;
                upk2(lo, hi, acc[i][j]);
                float2 o;
                o.x = lo + bc[c];
                o.y = hi + bc[c + 1];
                *(float2*)&d_QKVS[gn * 256 + c] = o;
            }
        }
    }
}

// ---------------- single-pass edge kernel with 2-deep software pipeline ----------------
__global__ void k_edge(int l) {
    __shared__ float et[640];
    for (int i = threadIdx.x; i < 640; i += blockDim.x) et[i] = d_ET[l * 640 + i];
    __syncthreads();

    int n = (blockIdx.x * blockDim.x + threadIdx.x) >> 5;
    int lane = threadIdx.x & 31;
    if (n >= Nn) return;
    int g = lane >> 3, r = lane & 7;
    unsigned gmask = 0xffu << (g * 8);
    int s0 = d_OFF[n], s1 = d_OFF[n + 1];
    int co = r * 8;

    if (s0 == s1) {          // isolated node: h = relu(skip)
        if (g == 0) {
            float4 sk0 = *(const float4*)&d_QKVS[n * 256 + 192 + co];
            float4 sk1 = *(const float4*)&d_QKVS[n * 256 + 192 + co + 4];
            float4 o0, o1;
            o0.x = fmaxf(sk0.x, 0.f); o0.y = fmaxf(sk0.y, 0.f);
            o0.z = fmaxf(sk0.z, 0.f); o0.w = fmaxf(sk0.w, 0.f);
            o1.x = fmaxf(sk1.x, 0.f); o1.y = fmaxf(sk1.y, 0.f);
            o1.z = fmaxf(sk1.z, 0.f); o1.w = fmaxf(sk1.w, 0.f);
            *(float4*)&d_H[n * 64 + co] = o0;
            *(float4*)&d_H[n * 64 + co + 4] = o1;
        }
        return;
    }

    float4 q0 = *(const float4*)&d_QKVS[n * 256 + co];
    float4 q1 = *(const float4*)&d_QKVS[n * 256 + co + 4];

    float m = -CUDART_INF_F, ssum = 0.f;
    float a[8];
    #pragma unroll
    for (int c = 0; c < 8; c++) a[c] = 0.f;

    // pipeline: pk two stages ahead, k/v one stage ahead
    int iA = s0 + g;
    bool vA = iA < s1;
    unsigned pkA = vA ? __ldg(&d_EPK[iA]) : 0u;
    int iB = iA + 4;
    bool vB = iB < s1;
    unsigned pkB = vB ? __ldg(&d_EPK[iB]) : 0u;
    float4 k0A, k1A, v0A, v1A;
    if (vA) {
        const float4* b = (const float4*)&d_QKVS[(pkA & 0xffffu) * 256 + 64 + co];
        k0A = __ldg(b); k1A = __ldg(b + 1); v0A = __ldg(b + 16); v1A = __ldg(b + 17);
    }

    while (vA) {
        // prefetch stage B's rows + stage C's index
        float4 k0B, k1B, v0B, v1B;
        if (vB) {
            const float4* b = (const float4*)&d_QKVS[(pkB & 0xffffu) * 256 + 64 + co];
            k0B = __ldg(b); k1B = __ldg(b + 1); v0B = __ldg(b + 16); v1B = __ldg(b + 17);
        }
        int iC = iB + 4;
        bool vC = iC < s1;
        unsigned pkC = vC ? __ldg(&d_EPK[iC]) : 0u;

        // compute on stage A
        int ty = pkA >> 16;
        float4 e0 = *(const float4*)&et[ty * 64 + co];
        float4 e1 = *(const float4*)&et[ty * 64 + co + 4];
        float d = q0.x * (k0A.x + e0.x) + q0.y * (k0A.y + e0.y)
                + q0.z * (k0A.z + e0.z) + q0.w * (k0A.w + e0.w)
                + q1.x * (k1A.x + e1.x) + q1.y * (k1A.y + e1.y)
                + q1.z * (k1A.z + e1.z) + q1.w * (k1A.w + e1.w);
        d += __shfl_xor_sync(gmask, d, 1);
        d += __shfl_xor_sync(gmask, d, 2);
        d += __shfl_xor_sync(gmask, d, 4);
        d *= 0.125f;
        float mn = fmaxf(m, d);
        float fac = __expf(m - mn);
        float p = __expf(d - mn);
        ssum = ssum * fac + p;
        a[0] = a[0] * fac + p * (v0A.x + e0.x);
        a[1] = a[1] * fac + p * (v0A.y + e0.y);
        a[2] = a[2] * fac + p * (v0A.z + e0.z);
        a[3] = a[3] * fac + p * (v0A.w + e0.w);
        a[4] = a[4] * fac + p * (v1A.x + e1.x);
        a[5] = a[5] * fac + p * (v1A.y + e1.y);
        a[6] = a[6] * fac + p * (v1A.z + e1.z);
        a[7] = a[7] * fac + p * (v1A.w + e1.w);
        m = mn;

        // rotate pipeline
        pkA = pkB; vA = vB;
        k0A = k0B; k1A = k1B; v0A = v0B; v1A = v1B;
        pkB = pkC; vB = vC; iB = iC;
    }

    // combine the 4 groups
    float M = fmaxf(m, __shfl_xor_sync(0xffffffffu, m, 8));
    M = fmaxf(M, __shfl_xor_sync(0xffffffffu, M, 16));
    float fac = __expf(m - M);           // 0 for empty groups (m = -inf)
    ssum *= fac;
    ssum += __shfl_xor_sync(0xffffffffu, ssum, 8);
    ssum += __shfl_xor_sync(0xffffffffu, ssum, 16);
    #pragma unroll
    for (int c = 0; c < 8; c++) {
        a[c] *= fac;
        a[c] += __shfl_xor_sync(0xffffffffu, a[c], 8);
        a[c] += __shfl_xor_sync(0xffffffffu, a[c], 16);
    }
    float inv = 1.f / ssum;

    if (g == 0) {
        float4 sk0 = *(const float4*)&d_QKVS[n * 256 + 192 + co];
        float4 sk1 = *(const float4*)&d_QKVS[n * 256 + 192 + co + 4];
        float4 o0, o1;
        o0.x = fmaxf(a[0] * inv + sk0.x, 0.f);
        o0.y = fmaxf(a[1] * inv + sk0.y, 0.f);
        o0.z = fmaxf(a[2] * inv + sk0.z, 0.f);
        o0.w = fmaxf(a[3] * inv + sk0.w, 0.f);
        o1.x = fmaxf(a[4] * inv + sk1.x, 0.f);
        o1.y = fmaxf(a[5] * inv + sk1.y, 0.f);
        o1.z = fmaxf(a[6] * inv + sk1.z, 0.f);
        o1.w = fmaxf(a[7] * inv + sk1.w, 0.f);
        *(float4*)&d_H[n * 64 + co] = o0;
        *(float4*)&d_H[n * 64 + co + 4] = o1;
    }
}

// ---------------- merged readout: y + gate + per-graph max ----------------
__global__ void k_outy(const float* __restrict__ out_W, const float* __restrict__ out_b,
                       const float* __restrict__ gW, const float* __restrict__ gb,
                       const int* __restrict__ batch) {
    __shared__ float Wm[64 * OUTd];
    __shared__ float gws[64];
    __shared__ float bb[OUTd];
    for (int i = threadIdx.x; i < 64 * OUTd; i += 256) Wm[i] = out_W[i];
    if (threadIdx.x < 64) gws[threadIdx.x] = gW[threadIdx.x];
    if (threadIdx.x < OUTd) bb[threadIdx.x] = out_b[threadIdx.x];
    __syncthreads();
    int n = blockIdx.x * 8 + (threadIdx.x >> 5);
    int c = threadIdx.x & 31;
    if (n >= Nn) return;
    float h0 = d_H[n * 64 + c];
    float h1 = d_H[n * 64 + 32 + c];
    float s = bb[c];
    #pragma unroll
    for (int kk = 0; kk < 32; kk++) {
        s += __shfl_sync(0xffffffffu, h0, kk) * Wm[kk * OUTd + c];
        s += __shfl_sync(0xffffffffu, h1, kk) * Wm[(32 + kk) * OUTd + c];
    }
    d_Y[n * OUTd + c] = s;
    float gv = h0 * gws[c] + h1 * gws[32 + c];
    #pragma unroll
    for (int o = 16; o; o >>= 1) gv += __shfl_xor_sync(0xffffffffu, gv, o);
    gv += gb[0];
    if (c == 0) {
        d_GATE[n] = gv;
        atomicMax(&d_GKEY[batch[n]], fkey(gv));
    }
}

// exp + weighted accumulate (merged)
__global__ void k_gacc2(const int* __restrict__ batch) {
    int i = blockIdx.x * blockDim.x + threadIdx.x;
    if (i >= Nn * OUTd) return;
    int n = i >> 5, c = i & 31;
    int b = batch[n];
    float p = __expf(d_GATE[n] - fdecode(d_GKEY[b]));
    atomicAdd(&d_OSUM[b * OUTd + c], p * d_Y[i]);
    if (c == 0) atomicAdd(&d_GDEN[b], p);
}

__global__ void k_final(float* __restrict__ out) {
    int i = blockIdx.x * blockDim.x + threadIdx.x;
    if (i >= Gg * OUTd) return;
    float den = d_GDEN[i >> 5];
    out[i] = (den > 0.f) ? d_OSUM[i] / den : 0.f;
}

// ---------------- launch ----------------
extern "C" void kernel_launch(void* const* d_in, const int* in_sizes, int n_in,
                              void* d_out, int out_size) {
    const int*   x        = (const int*)d_in[0];
    const int*   ei       = (const int*)d_in[1];
    const int*   ea       = (const int*)d_in[2];
    const int*   batch    = (const int*)d_in[3];
    const float* node_emb = (const float*)d_in[4];
    const float* edge_emb = (const float*)d_in[5];
    const float* Wq       = (const float*)d_in[6];
    const float* Wk       = (const float*)d_in[7];
    const float* Wv       = (const float*)d_in[8];
    const float* We       = (const float*)d_in[9];
    const float* Wskip    = (const float*)d_in[10];
    const float* bq       = (const float*)d_in[11];
    const float* bk       = (const float*)d_in[12];
    const float* bv       = (const float*)d_in[13];
    const float* bskip    = (const float*)d_in[14];
    const float* gate_W   = (const float*)d_in[15];
    const float* gate_b   = (const float*)d_in[16];
    const float* out_W    = (const float*)d_in[17];
    const float* out_b    = (const float*)d_in[18];
    float* out = (float*)d_out;

    const int* srcp = ei;
    const int* dstp = ei + Ee;

    static bool attr_set = false;
    if (!attr_set) {
        cudaFuncSetAttribute(k_gemm, cudaFuncAttributeMaxDynamicSharedMemorySize, 74752);
        attr_set = true;
    }

    // 1..5: prep + CSR  (k_gemm is launch #6 -> captured by ncu -s 5 -c 1)
    k_prep<<<(Nn * 64 + 255) / 256, 256>>>(x, node_emb, dstp, edge_emb, We);
    k_scan1<<<NB, 1024>>>();
    k_scan2<<<1, 32>>>();
    k_scan3<<<(Nn + 255) / 256, 256>>>();
    k_scatter<<<(Ee + 255) / 256, 256>>>(srcp, dstp, ea);

    for (int l = 0; l < Ll; l++) {
        k_gemm<<<(Nn + 31) / 32, 256, 74752>>>(Wq, Wk, Wv, Wskip, bq, bk, bv, bskip, l);
        k_edge<<<(Nn * 32 + 255) / 256, 256>>>(l);
    }

    k_outy<<<(Nn + 7) / 8, 256>>>(out_W, out_b, gate_W, gate_b, batch);
    k_gacc2<<<(Nn * OUTd + 255) / 256, 256>>>(batch);
    k_final<<<(Gg * OUTd + 255) / 256, 256>>>(out);
}

// round 7
// speedup vs baseline: 2.0356x; 1.2455x over previous
#include <cuda_runtime.h>
#include <cuda_fp16.h>
#include <math_constants.h>

#define Nn 50000
#define Ee 800000
#define Hh 64
#define EDd 32
#define Ll 3
#define Gg 256
#define OUTd 32
#define NB 49   // ceil(Nn/1024)

// ---------------- static device scratch ----------------
__device__ float  d_QS[Nn * 128];    // q(0..63) | skip(64..127), fp32
__device__ __half d_KV[Nn * 128];    // k(0..63) | v(64..127), fp16
__device__ float  d_H[Nn * 64];      // node features
__device__ int    d_CNT[Nn];         // zeroed by k_scan1 for next replay
__device__ int    d_CUR[Nn];
__device__ int    d_OFF[Nn + 1];
__device__ int    d_BT[64];          // scan block totals
__device__ unsigned d_EPK[Ee];       // CSR slots: src | (attr<<16)
__device__ float  d_ET[Ll * 640];    // per-layer edge-type tables (10 types x 64)
__device__ unsigned d_GKEY[Gg];
__device__ float  d_GDEN[Gg];
__device__ float  d_OSUM[Gg * OUTd];
__device__ float  d_GATE[Nn];
__device__ float  d_Y[Nn * OUTd];

// ---------------- helpers ----------------
__device__ __forceinline__ unsigned fkey(float f) {
    unsigned u = __float_as_uint(f);
    return (u & 0x80000000u) ? ~u : (u | 0x80000000u);
}
__device__ __forceinline__ float fdecode(unsigned k) {
    return (k & 0x80000000u) ? __uint_as_float(k & 0x7fffffffu) : __uint_as_float(~k);
}
__device__ __forceinline__ unsigned long long pk2(float lo, float hi) {
    unsigned long long r;
    asm("mov.b64 %0, {%1, %2};" : "=l"(r) : "f"(lo), "f"(hi));
    return r;
}
__device__ __forceinline__ void upk2(float& lo, float& hi, unsigned long long v) {
    asm("mov.b64 {%0, %1}, %2;" : "=f"(lo), "=f"(hi) : "l"(v));
}
__device__ __forceinline__ void ffma2(unsigned long long& acc, unsigned long long a,
                                      unsigned long long b) {
    asm("fma.rn.f32x2 %0, %1, %2, %0;" : "+l"(acc) : "l"(a), "l"(b));
}

// ---------------- prep: embed + hist + etab + zero readout scratch ----------------
__global__ void k_prep(const int* __restrict__ x, const float* __restrict__ node_emb,
                       const int* __restrict__ dst,
                       const float* __restrict__ edge_emb, const float* __restrict__ We) {
    int i = blockIdx.x * blockDim.x + threadIdx.x;
    if (i < Nn * 64) {
        int n = i >> 6, c = i & 63;
        d_H[i] = node_emb[x[n] * 64 + c];
    }
    if (i < Ee) atomicAdd(&d_CNT[dst[i]], 1);
    if (i < Ll * 640) {
        int l = i / 640, t = i % 640;
        int ty = t >> 6, c = t & 63;
        const float* W = We + l * (EDd * 64);
        float s = 0.f;
        #pragma unroll
        for (int j = 0; j < EDd; j++) s += edge_emb[ty * EDd + j] * W[j * 64 + c];
        d_ET[i] = s;
    }
    if (i < Gg) { d_GKEY[i] = 0u; d_GDEN[i] = 0.f; }
    if (i < Gg * OUTd) d_OSUM[i] = 0.f;
}

// ---------------- CSR scan (proven 3-kernel version, self-cleaning) ----------------
__global__ void k_scan1() {
    __shared__ int wsum[32];
    int t = threadIdx.x, b = blockIdx.x;
    int i = b * 1024 + t;
    int v = (i < Nn) ? d_CNT[i] : 0;
    int lane = t & 31, w = t >> 5;
    int x = v;
    #pragma unroll
    for (int o = 1; o < 32; o <<= 1) {
        int y = __shfl_up_sync(0xffffffffu, x, o);
        if (lane >= o) x += y;
    }
    if (lane == 31) wsum[w] = x;
    __syncthreads();
    if (w == 0) {
        int s = wsum[lane];
        #pragma unroll
        for (int o = 1; o < 32; o <<= 1) {
            int y = __shfl_up_sync(0xffffffffu, s, o);
            if (lane >= o) s += y;
        }
        wsum[lane] = s;
    }
    __syncthreads();
    int excl = x - v + (w ? wsum[w - 1] : 0);
    if (i < Nn) {
        d_OFF[i] = excl;
        d_CNT[i] = 0;      // ready for next replay
        d_CUR[i] = 0;
    }
    if (t == 1023) d_BT[b] = excl + v;
}

__global__ void k_scan2() {
    if (threadIdx.x == 0) {
        int s = 0;
        for (int b = 0; b < NB; b++) { int v = d_BT[b]; d_BT[b] = s; s += v; }
        d_OFF[Nn] = s;
    }
}

__global__ void k_scan3() {
    int i = blockIdx.x * blockDim.x + threadIdx.x;
    if (i < Nn) d_OFF[i] += d_BT[i >> 10];
}

__global__ void k_scatter(const int* __restrict__ src, const int* __restrict__ dst,
                          const int* __restrict__ attr) {
    int e = blockIdx.x * blockDim.x + threadIdx.x;
    if (e >= Ee) return;
    int d = dst[e];
    int p = atomicAdd(&d_CUR[d], 1);
    d_EPK[d_OFF[d] + p] = (unsigned)src[e] | ((unsigned)attr[e] << 16);
}

// ---------------- fused q,k,v,skip GEMM; q/skip -> fp32, k/v -> fp16 ----------------
__global__ void k_gemm(const float* __restrict__ Wq, const float* __restrict__ Wk,
                       const float* __restrict__ Wv, const float* __restrict__ Ws,
                       const float* __restrict__ bq, const float* __restrict__ bk,
                       const float* __restrict__ bv, const float* __restrict__ bs, int l) {
    extern __shared__ float smem[];
    float* Wc = smem;              // 16384 floats: [k][256]
    float* bc = smem + 16384;      // 256
    float* hs = smem + 16640;      // 2048
    int t = threadIdx.x;

    for (int m = 0; m < 4; m++) {
        const float* W = (m == 0 ? Wq : m == 1 ? Wk : m == 2 ? Wv : Ws) + l * 4096;
        for (int i = t; i < 4096; i += 256) {
            int kk = i >> 6, cc = i & 63;
            Wc[kk * 256 + m * 64 + cc] = W[kk * 64 + cc];
        }
    }
    {
        const float* B = (t < 64) ? bq : (t < 128) ? bk : (t < 192) ? bv : bs;
        bc[t] = B[l * 64 + (t & 63)];
    }
    int node0 = blockIdx.x * 32;
    for (int i = t; i < 32 * 64; i += 256) {
        int n = i >> 6, kk = i & 63;
        int gn = node0 + n;
        hs[i] = (gn < Nn) ? __ldg(&d_H[gn * 64 + kk]) : 0.f;
    }
    __syncthreads();

    int lane = t & 31, warp = t >> 5;
    unsigned long long acc[4][4];
    #pragma unroll
    for (int i = 0; i < 4; i++)
        #pragma unroll
        for (int j = 0; j < 4; j++) acc[i][j] = 0ull;

    #pragma unroll 8
    for (int kk = 0; kk < 64; kk++) {
        unsigned long long hp[4];
        #pragma unroll
        for (int i = 0; i < 4; i++) {
            float hv = hs[(warp * 4 + i) * 64 + kk];
            hp[i] = pk2(hv, hv);
        }
        #pragma unroll
        for (int j = 0; j < 4; j++) {
            unsigned long long wv =
                *(const unsigned long long*)&Wc[kk * 256 + j * 64 + 2 * lane];
            #pragma unroll
            for (int i = 0; i < 4; i++) ffma2(acc[i][j], hp[i], wv);
        }
    }
    #pragma unroll
    for (int i = 0; i < 4; i++) {
        int gn = node0 + warp * 4 + i;
        if (gn < Nn) {
            float r[4][2];
            #pragma unroll
            for (int j = 0; j < 4; j++) {
                float lo, hi;
                upk2(lo, hi, acc[i][j]);
                r[j][0] = lo + bc[j * 64 + 2 * lane];
                r[j][1] = hi + bc[j * 64 + 2 * lane + 1];
            }
            // j0=q (f32), j1=k (f16), j2=v (f16), j3=skip (f32)
            *(float2*)&d_QS[gn * 128 + 2 * lane] = make_float2(r[0][0], r[0][1]);
            *(float2*)&d_QS[gn * 128 + 64 + 2 * lane] = make_float2(r[3][0], r[3][1]);
            *(__half2*)&d_KV[gn * 128 + 2 * lane] = __floats2half2_rn(r[1][0], r[1][1]);
            *(__half2*)&d_KV[gn * 128 + 64 + 2 * lane] = __floats2half2_rn(r[2][0], r[2][1]);
        }
    }
}

// ---------------- single-pass edge kernel: fp16 k/v gather + online softmax ----------------
__global__ void k_edge(int l) {
    __shared__ float et[640];
    for (int i = threadIdx.x; i < 640; i += blockDim.x) et[i] = d_ET[l * 640 + i];
    __syncthreads();

    int n = (blockIdx.x * blockDim.x + threadIdx.x) >> 5;
    int lane = threadIdx.x & 31;
    if (n >= Nn) return;
    int g = lane >> 3, r = lane & 7;
    unsigned gmask = 0xffu << (g * 8);
    int s0 = d_OFF[n], s1 = d_OFF[n + 1];
    int co = r * 8;

    if (s0 == s1) {          // isolated node: h = relu(skip)
        if (g == 0) {
            float4 sk0 = *(const float4*)&d_QS[n * 128 + 64 + co];
            float4 sk1 = *(const float4*)&d_QS[n * 128 + 64 + co + 4];
            float4 o0, o1;
            o0.x = fmaxf(sk0.x, 0.f); o0.y = fmaxf(sk0.y, 0.f);
            o0.z = fmaxf(sk0.z, 0.f); o0.w = fmaxf(sk0.w, 0.f);
            o1.x = fmaxf(sk1.x, 0.f); o1.y = fmaxf(sk1.y, 0.f);
            o1.z = fmaxf(sk1.z, 0.f); o1.w = fmaxf(sk1.w, 0.f);
            *(float4*)&d_H[n * 64 + co] = o0;
            *(float4*)&d_H[n * 64 + co + 4] = o1;
        }
        return;
    }

    float4 q0 = *(const float4*)&d_QS[n * 128 + co];
    float4 q1 = *(const float4*)&d_QS[n * 128 + co + 4];

    float m = -CUDART_INF_F, ssum = 0.f;
    float a[8];
    #pragma unroll
    for (int c = 0; c < 8; c++) a[c] = 0.f;

    // pipeline: pk two stages ahead, k/v one stage ahead
    // KV row = 128 halfs = 16 uint4; k at uint4 offset r*... lane covers halfs
    // co..co+7 => uint4 index co/8 + r? co halfs = co*2 bytes; uint4 = 8 halfs.
    // &d_KV[s*128 + co] cast to uint4* is the k part; v is +64 halfs = +8 uint4.
    int iA = s0 + g;
    bool vA = iA < s1;
    unsigned pkA = vA ? __ldg(&d_EPK[iA]) : 0u;
    int iB = iA + 4;
    bool vB = iB < s1;
    unsigned pkB = vB ? __ldg(&d_EPK[iB]) : 0u;
    uint4 kA, vvA;
    if (vA) {
        const uint4* b = (const uint4*)&d_KV[(pkA & 0xffffu) * 128 + co];
        kA = __ldg(b); vvA = __ldg(b + 8);   // +8 uint4 = +64 halfs (v block)
    }

    while (vA) {
        uint4 kB, vvB;
        if (vB) {
            const uint4* b = (const uint4*)&d_KV[(pkB & 0xffffu) * 128 + co];
            kB = __ldg(b); vvB = __ldg(b + 8);
        }
        int iC = iB + 4;
        bool vC = iC < s1;
        unsigned pkC = vC ? __ldg(&d_EPK[iC]) : 0u;

        int ty = pkA >> 16;
        float4 e0 = *(const float4*)&et[ty * 64 + co];
        float4 e1 = *(const float4*)&et[ty * 64 + co + 4];
        float2 kx = __half22float2(*(__half2*)&kA.x);
        float2 ky = __half22float2(*(__half2*)&kA.y);
        float2 kz = __half22float2(*(__half2*)&kA.z);
        float2 kw = __half22float2(*(__half2*)&kA.w);
        float d = q0.x * (kx.x + e0.x) + q0.y * (kx.y + e0.y)
                + q0.z * (ky.x + e0.z) + q0.w * (ky.y + e0.w)
                + q1.x * (kz.x + e1.x) + q1.y * (kz.y + e1.y)
                + q1.z * (kw.x + e1.z) + q1.w * (kw.y + e1.w);
        d += __shfl_xor_sync(gmask, d, 1);
        d += __shfl_xor_sync(gmask, d, 2);
        d += __shfl_xor_sync(gmask, d, 4);
        d *= 0.125f;
        float mn = fmaxf(m, d);
        float fac = __expf(m - mn);
        float p = __expf(d - mn);
        ssum = ssum * fac + p;
        float2 vx = __half22float2(*(__half2*)&vvA.x);
        float2 vy = __half22float2(*(__half2*)&vvA.y);
        float2 vz = __half22float2(*(__half2*)&vvA.z);
        float2 vw = __half22float2(*(__half2*)&vvA.w);
        a[0] = a[0] * fac + p * (vx.x + e0.x);
        a[1] = a[1] * fac + p * (vx.y + e0.y);
        a[2] = a[2] * fac + p * (vy.x + e0.z);
        a[3] = a[3] * fac + p * (vy.y + e0.w);
        a[4] = a[4] * fac + p * (vz.x + e1.x);
        a[5] = a[5] * fac + p * (vz.y + e1.y);
        a[6] = a[6] * fac + p * (vw.x + e1.z);
        a[7] = a[7] * fac + p * (vw.y + e1.w);
        m = mn;

        pkA = pkB; vA = vB;
        kA = kB; vvA = vvB;
        pkB = pkC; vB = vC; iB = iC;
    }

    // combine the 4 groups
    float M = fmaxf(m, __shfl_xor_sync(0xffffffffu, m, 8));
    M = fmaxf(M, __shfl_xor_sync(0xffffffffu, M, 16));
    float fac = __expf(m - M);           // 0 for empty groups (m = -inf)
    ssum *= fac;
    ssum += __shfl_xor_sync(0xffffffffu, ssum, 8);
    ssum += __shfl_xor_sync(0xffffffffu, ssum, 16);
    #pragma unroll
    for (int c = 0; c < 8; c++) {
        a[c] *= fac;
        a[c] += __shfl_xor_sync(0xffffffffu, a[c], 8);
        a[c] += __shfl_xor_sync(0xffffffffu, a[c], 16);
    }
    float inv = 1.f / ssum;

    if (g == 0) {
        float4 sk0 = *(const float4*)&d_QS[n * 128 + 64 + co];
        float4 sk1 = *(const float4*)&d_QS[n * 128 + 64 + co + 4];
        float4 o0, o1;
        o0.x = fmaxf(a[0] * inv + sk0.x, 0.f);
        o0.y = fmaxf(a[1] * inv + sk0.y, 0.f);
        o0.z = fmaxf(a[2] * inv + sk0.z, 0.f);
        o0.w = fmaxf(a[3] * inv + sk0.w, 0.f);
        o1.x = fmaxf(a[4] * inv + sk1.x, 0.f);
        o1.y = fmaxf(a[5] * inv + sk1.y, 0.f);
        o1.z = fmaxf(a[6] * inv + sk1.z, 0.f);
        o1.w = fmaxf(a[7] * inv + sk1.w, 0.f);
        *(float4*)&d_H[n * 64 + co] = o0;
        *(float4*)&d_H[n * 64 + co + 4] = o1;
    }
}

// ---------------- merged readout: y + gate + per-graph max ----------------
__global__ void k_outy(const float* __restrict__ out_W, const float* __restrict__ out_b,
                       const float* __restrict__ gW, const float* __restrict__ gb,
                       const int* __restrict__ batch) {
    __shared__ float Wm[64 * OUTd];
    __shared__ float gws[64];
    __shared__ float bb[OUTd];
    for (int i = threadIdx.x; i < 64 * OUTd; i += 256) Wm[i] = out_W[i];
    if (threadIdx.x < 64) gws[threadIdx.x] = gW[threadIdx.x];
    if (threadIdx.x < OUTd) bb[threadIdx.x] = out_b[threadIdx.x];
    __syncthreads();
    int n = blockIdx.x * 8 + (threadIdx.x >> 5);
    int c = threadIdx.x & 31;
    if (n >= Nn) return;
    float h0 = d_H[n * 64 + c];
    float h1 = d_H[n * 64 + 32 + c];
    float s = bb[c];
    #pragma unroll
    for (int kk = 0; kk < 32; kk++) {
        s += __shfl_sync(0xffffffffu, h0, kk) * Wm[kk * OUTd + c];
        s += __shfl_sync(0xffffffffu, h1, kk) * Wm[(32 + kk) * OUTd + c];
    }
    d_Y[n * OUTd + c] = s;
    float gv = h0 * gws[c] + h1 * gws[32 + c];
    #pragma unroll
    for (int o = 16; o; o >>= 1) gv += __shfl_xor_sync(0xffffffffu, gv, o);
    gv += gb[0];
    if (c == 0) {
        d_GATE[n] = gv;
        atomicMax(&d_GKEY[batch[n]], fkey(gv));
    }
}

__global__ void k_gacc2(const int* __restrict__ batch) {
    int i = blockIdx.x * blockDim.x + threadIdx.x;
    if (i >= Nn * OUTd) return;
    int n = i >> 5, c = i & 31;
    int b = batch[n];
    float p = __expf(d_GATE[n] - fdecode(d_GKEY[b]));
    atomicAdd(&d_OSUM[b * OUTd + c], p * d_Y[i]);
    if (c == 0) atomicAdd(&d_GDEN[b], p);
}

__global__ void k_final(float* __restrict__ out) {
    int i = blockIdx.x * blockDim.x + threadIdx.x;
    if (i >= Gg * OUTd) return;
    float den = d_GDEN[i >> 5];
    out[i] = (den > 0.f) ? d_OSUM[i] / den : 0.f;
}

// ---------------- launch ----------------
extern "C" void kernel_launch(void* const* d_in, const int* in_sizes, int n_in,
                              void* d_out, int out_size) {
    const int*   x        = (const int*)d_in[0];
    const int*   ei       = (const int*)d_in[1];
    const int*   ea       = (const int*)d_in[2];
    const int*   batch    = (const int*)d_in[3];
    const float* node_emb = (const float*)d_in[4];
    const float* edge_emb = (const float*)d_in[5];
    const float* Wq       = (const float*)d_in[6];
    const float* Wk       = (const float*)d_in[7];
    const float* Wv       = (const float*)d_in[8];
    const float* We       = (const float*)d_in[9];
    const float* Wskip    = (const float*)d_in[10];
    const float* bq       = (const float*)d_in[11];
    const float* bk       = (const float*)d_in[12];
    const float* bv       = (const float*)d_in[13];
    const float* bskip    = (const float*)d_in[14];
    const float* gate_W   = (const float*)d_in[15];
    const float* gate_b   = (const float*)d_in[16];
    const float* out_W    = (const float*)d_in[17];
    const float* out_b    = (const float*)d_in[18];
    float* out = (float*)d_out;

    const int* srcp = ei;
    const int* dstp = ei + Ee;

    static bool attr_set = false;
    if (!attr_set) {
        cudaFuncSetAttribute(k_gemm, cudaFuncAttributeMaxDynamicSharedMemorySize, 74752);
        attr_set = true;
    }

    k_prep<<<(Nn * 64 + 255) / 256, 256>>>(x, node_emb, dstp, edge_emb, We);
    k_scan1<<<NB, 1024>>>();
    k_scan2<<<1, 32>>>();
    k_scan3<<<(Nn + 255) / 256, 256>>>();
    k_scatter<<<(Ee + 255) / 256, 256>>>(srcp, dstp, ea);

    for (int l = 0; l < Ll; l++) {
        k_gemm<<<(Nn + 31) / 32, 256, 74752>>>(Wq, Wk, Wv, Wskip, bq, bk, bv, bskip, l);
        k_edge<<<(Nn * 32 + 255) / 256, 256>>>(l);
    }

    k_outy<<<(Nn + 7) / 8, 256>>>(out_W, out_b, gate_W, gate_b, batch);
    k_gacc2<<<(Nn * OUTd + 255) / 256, 256>>>(batch);
    k_final<<<(Gg * OUTd + 255) / 256, 256>>>(out);
}

// round 8
// speedup vs baseline: 2.3560x; 1.1574x over previous
#include <cuda_runtime.h>
#include <cuda_fp16.h>
#include <math_constants.h>

#define Nn 50000
#define Ee 800000
#define Hh 64
#define EDd 32
#define Ll 3
#define Gg 256
#define OUTd 32
#define NB 49   // ceil(Nn/1024)

// ---------------- static device scratch ----------------
__device__ float  d_QS[Nn * 128];    // q(0..63) | skip(64..127), fp32
__device__ __half d_KV[Nn * 128];    // k(0..63) | v(64..127), fp16
__device__ float  d_H[Nn * 64];      // node features
__device__ int    d_CNT[Nn];         // zeroed by k_scan1 for next replay
__device__ int    d_CUR[Nn];
__device__ int    d_OFF[Nn + 1];
__device__ int    d_BT[64];          // scan block totals
__device__ unsigned d_EPK[Ee];       // CSR slots: src | (attr<<16)
__device__ float  d_ET[Ll * 640];    // per-layer edge-type tables (10 types x 64)
__device__ unsigned d_GKEY[Gg];
__device__ float  d_GDEN[Gg];
__device__ float  d_OSUM[Gg * OUTd];
__device__ float  d_GATE[Nn];
__device__ float  d_Y[Nn * OUTd];

// ---------------- helpers ----------------
__device__ __forceinline__ unsigned fkey(float f) {
    unsigned u = __float_as_uint(f);
    return (u & 0x80000000u) ? ~u : (u | 0x80000000u);
}
__device__ __forceinline__ float fdecode(unsigned k) {
    return (k & 0x80000000u) ? __uint_as_float(k & 0x7fffffffu) : __uint_as_float(~k);
}

// ---------------- prep: embed + hist + etab + zero readout scratch ----------------
__global__ void k_prep(const int* __restrict__ x, const float* __restrict__ node_emb,
                       const int* __restrict__ dst,
                       const float* __restrict__ edge_emb, const float* __restrict__ We) {
    int i = blockIdx.x * blockDim.x + threadIdx.x;
    if (i < Nn * 64) {
        int n = i >> 6, c = i & 63;
        d_H[i] = node_emb[x[n] * 64 + c];
    }
    if (i < Ee) atomicAdd(&d_CNT[dst[i]], 1);
    if (i < Ll * 640) {
        int l = i / 640, t = i % 640;
        int ty = t >> 6, c = t & 63;
        const float* W = We + l * (EDd * 64);
        float s = 0.f;
        #pragma unroll
        for (int j = 0; j < EDd; j++) s += edge_emb[ty * EDd + j] * W[j * 64 + c];
        d_ET[i] = s;
    }
    if (i < Gg) { d_GKEY[i] = 0u; d_GDEN[i] = 0.f; }
    if (i < Gg * OUTd) d_OSUM[i] = 0.f;
}

// ---------------- CSR scan (self-cleaning) ----------------
__global__ void k_scan1() {
    __shared__ int wsum[32];
    int t = threadIdx.x, b = blockIdx.x;
    int i = b * 1024 + t;
    int v = (i < Nn) ? d_CNT[i] : 0;
    int lane = t & 31, w = t >> 5;
    int x = v;
    #pragma unroll
    for (int o = 1; o < 32; o <<= 1) {
        int y = __shfl_up_sync(0xffffffffu, x, o);
        if (lane >= o) x += y;
    }
    if (lane == 31) wsum[w] = x;
    __syncthreads();
    if (w == 0) {
        int s = wsum[lane];
        #pragma unroll
        for (int o = 1; o < 32; o <<= 1) {
            int y = __shfl_up_sync(0xffffffffu, s, o);
            if (lane >= o) s += y;
        }
        wsum[lane] = s;
    }
    __syncthreads();
    int excl = x - v + (w ? wsum[w - 1] : 0);
    if (i < Nn) {
        d_OFF[i] = excl;
        d_CNT[i] = 0;
        d_CUR[i] = 0;
    }
    if (t == 1023) d_BT[b] = excl + v;
}

__global__ void k_scan2() {
    if (threadIdx.x == 0) {
        int s = 0;
        for (int b = 0; b < NB; b++) { int v = d_BT[b]; d_BT[b] = s; s += v; }
        d_OFF[Nn] = s;
    }
}

__global__ void k_scan3() {
    int i = blockIdx.x * blockDim.x + threadIdx.x;
    if (i < Nn) d_OFF[i] += d_BT[i >> 10];
}

__global__ void k_scatter(const int* __restrict__ src, const int* __restrict__ dst,
                          const int* __restrict__ attr) {
    int e = blockIdx.x * blockDim.x + threadIdx.x;
    if (e >= Ee) return;
    int d = dst[e];
    int p = atomicAdd(&d_CUR[d], 1);
    d_EPK[d_OFF[d] + p] = (unsigned)src[e] | ((unsigned)attr[e] << 16);
}

// ---------------- tensor-core q,k,v,skip GEMM (HMMA m16n8k16, fp16 in / fp32 acc) ----
// block: 256 thr = 8 warps. tile: 32 nodes x 256 cols.
// warp w: rows (w&1)*16..+16, matrix m = w>>1 (cols m*64..+64).
#define HS_STR 72   // halfs per hs row  (144B: +16B shift/row -> conflict-free frags)
#define WT_STR 72   // halfs per Wt row
__global__ void k_gemm(const float* __restrict__ Wq, const float* __restrict__ Wk,
                       const float* __restrict__ Wv, const float* __restrict__ Ws,
                       const float* __restrict__ bq, const float* __restrict__ bk,
                       const float* __restrict__ bv, const float* __restrict__ bs, int l) {
    extern __shared__ char smemc[];
    __half* hs = (__half*)smemc;                       // [32][HS_STR]
    __half* Wt = (__half*)(smemc + 32 * HS_STR * 2);   // [256][WT_STR]  (n-major, k contig)
    float*  bc = (float*)(smemc + 32 * HS_STR * 2 + 256 * WT_STR * 2);  // [256]
    int t = threadIdx.x;

    // W -> Wt (transposed, fp16): Wt[m*64+n][k] = W[k][n]
    for (int m = 0; m < 4; m++) {
        const float* W = (m == 0 ? Wq : m == 1 ? Wk : m == 2 ? Wv : Ws) + l * 4096;
        for (int i = t; i < 4096; i += 256) {
            int kk = i >> 6, cc = i & 63;
            Wt[(m * 64 + cc) * WT_STR + kk] = __float2half(W[kk * 64 + cc]);
        }
    }
    {
        const float* B = (t < 64) ? bq : (t < 128) ? bk : (t < 192) ? bv : bs;
        bc[t] = B[l * 64 + (t & 63)];
    }
    int node0 = blockIdx.x * 32;
    for (int i = t; i < 32 * 64; i += 256) {
        int n = i >> 6, kk = i & 63;
        int gn = node0 + n;
        hs[n * HS_STR + kk] = __float2half(gn < Nn ? __ldg(&d_H[gn * 64 + kk]) : 0.f);
    }
    __syncthreads();

    int lane = t & 31, w = t >> 5;
    int g = lane >> 2, t4 = lane & 3;
    int rbase = (w & 1) * 16;          // row offset within the 32-node tile
    int mtx = w >> 1;                  // 0=q 1=k 2=v 3=skip
    const __half* wrow0 = Wt + (mtx * 64) * WT_STR;

    float c0[8], c1[8], c2[8], c3[8];
    #pragma unroll
    for (int nt = 0; nt < 8; nt++) { c0[nt] = c1[nt] = c2[nt] = c3[nt] = 0.f; }

    #pragma unroll
    for (int ks = 0; ks < 4; ks++) {
        int k0 = ks * 16;
        // A fragment (16x16) from hs
        unsigned ra0 = *(const unsigned*)&hs[(rbase + g) * HS_STR + k0 + 2 * t4];
        unsigned ra1 = *(const unsigned*)&hs[(rbase + g + 8) * HS_STR + k0 + 2 * t4];
        unsigned ra2 = *(const unsigned*)&hs[(rbase + g) * HS_STR + k0 + 2 * t4 + 8];
        unsigned ra3 = *(const unsigned*)&hs[(rbase + g + 8) * HS_STR + k0 + 2 * t4 + 8];
        #pragma unroll
        for (int nt = 0; nt < 8; nt++) {
            const __half* wr = wrow0 + (nt * 8 + g) * WT_STR + k0;
            unsigned rb0 = *(const unsigned*)&wr[2 * t4];
            unsigned rb1 = *(const unsigned*)&wr[2 * t4 + 8];
            asm volatile(
                "mma.sync.aligned.m16n8k16.row.col.f32.f16.f16.f32 "
                "{%0,%1,%2,%3}, {%4,%5,%6,%7}, {%8,%9}, {%0,%1,%2,%3};"
                : "+f"(c0[nt]), "+f"(c1[nt]), "+f"(c2[nt]), "+f"(c3[nt])
                : "r"(ra0), "r"(ra1), "r"(ra2), "r"(ra3), "r"(rb0), "r"(rb1));
        }
    }

    // epilogue: row0 = g, row1 = g+8; cols nt*8 + 2*t4 (+1)
    int gn0 = node0 + rbase + g;
    int gn1 = gn0 + 8;
    #pragma unroll
    for (int nt = 0; nt < 8; nt++) {
        int col = nt * 8 + 2 * t4;
        float b0 = bc[mtx * 64 + col], b1 = bc[mtx * 64 + col + 1];
        float v00 = c0[nt] + b0, v01 = c1[nt] + b1;
        float v10 = c2[nt] + b0, v11 = c3[nt] + b1;
        if (mtx == 0) {
            if (gn0 < Nn) *(float2*)&d_QS[gn0 * 128 + col] = make_float2(v00, v01);
            if (gn1 < Nn) *(float2*)&d_QS[gn1 * 128 + col] = make_float2(v10, v11);
        } else if (mtx == 3) {
            if (gn0 < Nn) *(float2*)&d_QS[gn0 * 128 + 64 + col] = make_float2(v00, v01);
            if (gn1 < Nn) *(float2*)&d_QS[gn1 * 128 + 64 + col] = make_float2(v10, v11);
        } else {
            int off = (mtx == 1) ? 0 : 64;
            if (gn0 < Nn) *(__half2*)&d_KV[gn0 * 128 + off + col] = __floats2half2_rn(v00, v01);
            if (gn1 < Nn) *(__half2*)&d_KV[gn1 * 128 + off + col] = __floats2half2_rn(v10, v11);
        }
    }
}
#define GEMM_SMEM (32 * HS_STR * 2 + 256 * WT_STR * 2 + 256 * 4)

// ---------------- single-pass edge kernel: fp16 k/v gather + online softmax ----------------
__global__ void k_edge(int l) {
    __shared__ float et[640];
    for (int i = threadIdx.x; i < 640; i += blockDim.x) et[i] = d_ET[l * 640 + i];
    __syncthreads();

    int n = (blockIdx.x * blockDim.x + threadIdx.x) >> 5;
    int lane = threadIdx.x & 31;
    if (n >= Nn) return;
    int g = lane >> 3, r = lane & 7;
    unsigned gmask = 0xffu << (g * 8);
    int s0 = d_OFF[n], s1 = d_OFF[n + 1];
    int co = r * 8;

    if (s0 == s1) {          // isolated node: h = relu(skip)
        if (g == 0) {
            float4 sk0 = *(const float4*)&d_QS[n * 128 + 64 + co];
            float4 sk1 = *(const float4*)&d_QS[n * 128 + 64 + co + 4];
            float4 o0, o1;
            o0.x = fmaxf(sk0.x, 0.f); o0.y = fmaxf(sk0.y, 0.f);
            o0.z = fmaxf(sk0.z, 0.f); o0.w = fmaxf(sk0.w, 0.f);
            o1.x = fmaxf(sk1.x, 0.f); o1.y = fmaxf(sk1.y, 0.f);
            o1.z = fmaxf(sk1.z, 0.f); o1.w = fmaxf(sk1.w, 0.f);
            *(float4*)&d_H[n * 64 + co] = o0;
            *(float4*)&d_H[n * 64 + co + 4] = o1;
        }
        return;
    }

    float4 q0 = *(const float4*)&d_QS[n * 128 + co];
    float4 q1 = *(const float4*)&d_QS[n * 128 + co + 4];

    float m = -CUDART_INF_F, ssum = 0.f;
    float a[8];
    #pragma unroll
    for (int c = 0; c < 8; c++) a[c] = 0.f;

    int iA = s0 + g;
    bool vA = iA < s1;
    unsigned pkA = vA ? __ldg(&d_EPK[iA]) : 0u;
    int iB = iA + 4;
    bool vB = iB < s1;
    unsigned pkB = vB ? __ldg(&d_EPK[iB]) : 0u;
    uint4 kA, vvA;
    if (vA) {
        const uint4* b = (const uint4*)&d_KV[(pkA & 0xffffu) * 128 + co];
        kA = __ldg(b); vvA = __ldg(b + 8);   // +8 uint4 = +64 halfs (v block)
    }

    while (vA) {
        uint4 kB, vvB;
        if (vB) {
            const uint4* b = (const uint4*)&d_KV[(pkB & 0xffffu) * 128 + co];
            kB = __ldg(b); vvB = __ldg(b + 8);
        }
        int iC = iB + 4;
        bool vC = iC < s1;
        unsigned pkC = vC ? __ldg(&d_EPK[iC]) : 0u;

        int ty = pkA >> 16;
        float4 e0 = *(const float4*)&et[ty * 64 + co];
        float4 e1 = *(const float4*)&et[ty * 64 + co + 4];
        float2 kx = __half22float2(*(__half2*)&kA.x);
        float2 ky = __half22float2(*(__half2*)&kA.y);
        float2 kz = __half22float2(*(__half2*)&kA.z);
        float2 kw = __half22float2(*(__half2*)&kA.w);
        float d = q0.x * (kx.x + e0.x) + q0.y * (kx.y + e0.y)
                + q0.z * (ky.x + e0.z) + q0.w * (ky.y + e0.w)
                + q1.x * (kz.x + e1.x) + q1.y * (kz.y + e1.y)
                + q1.z * (kw.x + e1.z) + q1.w * (kw.y + e1.w);
        d += __shfl_xor_sync(gmask, d, 1);
        d += __shfl_xor_sync(gmask, d, 2);
        d += __shfl_xor_sync(gmask, d, 4);
        d *= 0.125f;
        float mn = fmaxf(m, d);
        float fac = __expf(m - mn);
        float p = __expf(d - mn);
        ssum = ssum * fac + p;
        float2 vx = __half22float2(*(__half2*)&vvA.x);
        float2 vy = __half22float2(*(__half2*)&vvA.y);
        float2 vz = __half22float2(*(__half2*)&vvA.z);
        float2 vw = __half22float2(*(__half2*)&vvA.w);
        a[0] = a[0] * fac + p * (vx.x + e0.x);
        a[1] = a[1] * fac + p * (vx.y + e0.y);
        a[2] = a[2] * fac + p * (vy.x + e0.z);
        a[3] = a[3] * fac + p * (vy.y + e0.w);
        a[4] = a[4] * fac + p * (vz.x + e1.x);
        a[5] = a[5] * fac + p * (vz.y + e1.y);
        a[6] = a[6] * fac + p * (vw.x + e1.z);
        a[7] = a[7] * fac + p * (vw.y + e1.w);
        m = mn;

        pkA = pkB; vA = vB;
        kA = kB; vvA = vvB;
        pkB = pkC; vB = vC; iB = iC;
    }

    // combine the 4 groups
    float M = fmaxf(m, __shfl_xor_sync(0xffffffffu, m, 8));
    M = fmaxf(M, __shfl_xor_sync(0xffffffffu, M, 16));
    float fac = __expf(m - M);           // 0 for empty groups (m = -inf)
    ssum *= fac;
    ssum += __shfl_xor_sync(0xffffffffu, ssum, 8);
    ssum += __shfl_xor_sync(0xffffffffu, ssum, 16);
    #pragma unroll
    for (int c = 0; c < 8; c++) {
        a[c] *= fac;
        a[c] += __shfl_xor_sync(0xffffffffu, a[c], 8);
        a[c] += __shfl_xor_sync(0xffffffffu, a[c], 16);
    }
    float inv = 1.f / ssum;

    if (g == 0) {
        float4 sk0 = *(const float4*)&d_QS[n * 128 + 64 + co];
        float4 sk1 = *(const float4*)&d_QS[n * 128 + 64 + co + 4];
        float4 o0, o1;
        o0.x = fmaxf(a[0] * inv + sk0.x, 0.f);
        o0.y = fmaxf(a[1] * inv + sk0.y, 0.f);
        o0.z = fmaxf(a[2] * inv + sk0.z, 0.f);
        o0.w = fmaxf(a[3] * inv + sk0.w, 0.f);
        o1.x = fmaxf(a[4] * inv + sk1.x, 0.f);
        o1.y = fmaxf(a[5] * inv + sk1.y, 0.f);
        o1.z = fmaxf(a[6] * inv + sk1.z, 0.f);
        o1.w = fmaxf(a[7] * inv + sk1.w, 0.f);
        *(float4*)&d_H[n * 64 + co] = o0;
        *(float4*)&d_H[n * 64 + co + 4] = o1;
    }
}

// ---------------- merged readout: y + gate + per-graph max ----------------
__global__ void k_outy(const float* __restrict__ out_W, const float* __restrict__ out_b,
                       const float* __restrict__ gW, const float* __restrict__ gb,
                       const int* __restrict__ batch) {
    __shared__ float Wm[64 * OUTd];
    __shared__ float gws[64];
    __shared__ float bb[OUTd];
    for (int i = threadIdx.x; i < 64 * OUTd; i += 256) Wm[i] = out_W[i];
    if (threadIdx.x < 64) gws[threadIdx.x] = gW[threadIdx.x];
    if (threadIdx.x < OUTd) bb[threadIdx.x] = out_b[threadIdx.x];
    __syncthreads();
    int n = blockIdx.x * 8 + (threadIdx.x >> 5);
    int c = threadIdx.x & 31;
    if (n >= Nn) return;
    float h0 = d_H[n * 64 + c];
    float h1 = d_H[n * 64 + 32 + c];
    float s = bb[c];
    #pragma unroll
    for (int kk = 0; kk < 32; kk++) {
        s += __shfl_sync(0xffffffffu, h0, kk) * Wm[kk * OUTd + c];
        s += __shfl_sync(0xffffffffu, h1, kk) * Wm[(32 + kk) * OUTd + c];
    }
    d_Y[n * OUTd + c] = s;
    float gv = h0 * gws[c] + h1 * gws[32 + c];
    #pragma unroll
    for (int o = 16; o; o >>= 1) gv += __shfl_xor_sync(0xffffffffu, gv, o);
    gv += gb[0];
    if (c == 0) {
        d_GATE[n] = gv;
        atomicMax(&d_GKEY[batch[n]], fkey(gv));
    }
}

__global__ void k_gacc2(const int* __restrict__ batch) {
    int i = blockIdx.x * blockDim.x + threadIdx.x;
    if (i >= Nn * OUTd) return;
    int n = i >> 5, c = i & 31;
    int b = batch[n];
    float p = __expf(d_GATE[n] - fdecode(d_GKEY[b]));
    atomicAdd(&d_OSUM[b * OUTd + c], p * d_Y[i]);
    if (c == 0) atomicAdd(&d_GDEN[b], p);
}

__global__ void k_final(float* __restrict__ out) {
    int i = blockIdx.x * blockDim.x + threadIdx.x;
    if (i >= Gg * OUTd) return;
    float den = d_GDEN[i >> 5];
    out[i] = (den > 0.f) ? d_OSUM[i] / den : 0.f;
}

// ---------------- launch ----------------
extern "C" void kernel_launch(void* const* d_in, const int* in_sizes, int n_in,
                              void* d_out, int out_size) {
    const int*   x        = (const int*)d_in[0];
    const int*   ei       = (const int*)d_in[1];
    const int*   ea       = (const int*)d_in[2];
    const int*   batch    = (const int*)d_in[3];
    const float* node_emb = (const float*)d_in[4];
    const float* edge_emb = (const float*)d_in[5];
    const float* Wq       = (const float*)d_in[6];
    const float* Wk       = (const float*)d_in[7];
    const float* Wv       = (const float*)d_in[8];
    const float* We       = (const float*)d_in[9];
    const float* Wskip    = (const float*)d_in[10];
    const float* bq       = (const float*)d_in[11];
    const float* bk       = (const float*)d_in[12];
    const float* bv       = (const float*)d_in[13];
    const float* bskip    = (const float*)d_in[14];
    const float* gate_W   = (const float*)d_in[15];
    const float* gate_b   = (const float*)d_in[16];
    const float* out_W    = (const float*)d_in[17];
    const float* out_b    = (const float*)d_in[18];
    float* out = (float*)d_out;

    const int* srcp = ei;
    const int* dstp = ei + Ee;

    static bool attr_set = false;
    if (!attr_set) {
        cudaFuncSetAttribute(k_gemm, cudaFuncAttributeMaxDynamicSharedMemorySize, GEMM_SMEM);
        attr_set = true;
    }

    k_prep<<<(Nn * 64 + 255) / 256, 256>>>(x, node_emb, dstp, edge_emb, We);
    k_scan1<<<NB, 1024>>>();
    k_scan2<<<1, 32>>>();
    k_scan3<<<(Nn + 255) / 256, 256>>>();
    k_scatter<<<(Ee + 255) / 256, 256>>>(srcp, dstp, ea);

    for (int l = 0; l < Ll; l++) {
        k_gemm<<<(Nn + 31) / 32, 256, GEMM_SMEM>>>(Wq, Wk, Wv, Wskip, bq, bk, bv, bskip, l);
        k_edge<<<(Nn * 32 + 255) / 256, 256>>>(l);
    }

    k_outy<<<(Nn + 7) / 8, 256>>>(out_W, out_b, gate_W, gate_b, batch);
    k_gacc2<<<(Nn * OUTd + 255) / 256, 256>>>(batch);
    k_final<<<(Gg * OUTd + 255) / 256, 256>>>(out);
}